// round 9
// baseline (speedup 1.0000x reference)
#include <cuda_runtime.h>
#include <cuda_fp16.h>
#include <cstdint>
#include <stdint.h>
#include <math.h>

#define Dm 1024
#define Fm 4096
#define Em 8
#define Tm 4096
#define MAXP (2 * Tm)
#define PADR 128

#define BM 128
#define BN 128
#define BK 32
#define AST (BK + 8)   // 40 halfs = 80B rows -> conflict-free ldmatrix, 16B-aligned
#define BST (BK + 8)
#define STAGE_H (BM * AST)            // halfs per A (or B) stage = 5120
#define SMEM_DYN (6 * STAGE_H * 2)    // 3 stages x (A+B) = 61440 bytes

// ---- scratch (device globals; allocation is forbidden) ----
__device__ __half g_W1h[(size_t)Em * Fm * Dm];      // W1 transposed fp16: [e][f][d]
__device__ __half g_W2h[(size_t)Em * Dm * Fm];      // W2 transposed fp16: [e][d][f]
__device__ __half g_Xg[(size_t)(MAXP + PADR) * Dm]; // gathered tokens fp16
__device__ __half g_H [(size_t)(MAXP + PADR) * Fm]; // GELU activations fp16
__device__ int   g_cnt[Em];
__device__ int   g_off[Em];
__device__ int   g_fill[Em];
__device__ int   g_tokid[MAXP];
__device__ float g_wt[MAXP];          // routing weight per slot
__device__ int   g_te[Tm];            // e0 | e1<<8
__device__ float g_tw[2 * Tm];        // routing weights per (token,k)

// ---------------- zero output + init counters ----------------
__global__ void zero_kernel(float* __restrict__ out) {
    int i = blockIdx.x * blockDim.x + threadIdx.x;
    ((float4*)out)[i] = make_float4(0.f, 0.f, 0.f, 0.f);
    if (blockIdx.x == 0 && threadIdx.x < Em) g_cnt[threadIdx.x] = 0;
}

// ---------------- router: logits -> top2 -> softmax ----------------
__global__ void route_kernel(const float* __restrict__ x,
                             const float* __restrict__ Wr,
                             const float* __restrict__ br) {
    int t = blockIdx.x;
    __shared__ float xs[Dm];
    __shared__ float logits[Em];
    for (int i = threadIdx.x; i < Dm; i += blockDim.x) xs[i] = x[(size_t)t * Dm + i];
    __syncthreads();
    int warp = threadIdx.x >> 5, lane = threadIdx.x & 31;
    if (warp < Em) {
        float s = 0.f;
        for (int d = lane; d < Dm; d += 32) s += xs[d] * Wr[d * Em + warp];
        #pragma unroll
        for (int o = 16; o; o >>= 1) s += __shfl_xor_sync(0xffffffffu, s, o);
        if (lane == 0) logits[warp] = s + br[warp];
    }
    __syncthreads();
    if (threadIdx.x == 0) {
        int i0 = 0; float v0 = logits[0];
        #pragma unroll
        for (int e = 1; e < Em; e++) if (logits[e] > v0) { v0 = logits[e]; i0 = e; }
        int i1 = -1; float v1 = -1e30f;
        #pragma unroll
        for (int e = 0; e < Em; e++) if (e != i0 && logits[e] > v1) { v1 = logits[e]; i1 = e; }
        float e1 = expf(v1 - v0);
        float inv = 1.0f / (1.0f + e1);
        atomicAdd(&g_cnt[i0], 1);
        atomicAdd(&g_cnt[i1], 1);
        g_te[t] = i0 | (i1 << 8);
        g_tw[2 * t]     = inv;
        g_tw[2 * t + 1] = e1 * inv;
    }
}

// ---------------- tiny exclusive scan over 8 counts ----------------
__global__ void scan_kernel() {
    int o = 0;
    for (int e = 0; e < Em; e++) { g_off[e] = o; g_fill[e] = o; o += g_cnt[e]; }
}

// ---------------- scatter token ids into compact per-expert slots ----------------
__global__ void scatter_kernel() {
    int t = blockIdx.x * blockDim.x + threadIdx.x;
    if (t >= Tm) return;
    int p = g_te[t];
    int e0 = p & 255, e1 = p >> 8;
    int s0 = atomicAdd(&g_fill[e0], 1);
    g_tokid[s0] = t; g_wt[s0] = g_tw[2 * t];
    int s1 = atomicAdd(&g_fill[e1], 1);
    g_tokid[s1] = t; g_wt[s1] = g_tw[2 * t + 1];
}

// ---------------- gather tokens into compact fp16 rows ----------------
__global__ void gather_kernel(const float* __restrict__ x) {
    int s = blockIdx.x;
    int tok = g_tokid[s];
    float4 v = ((const float4*)(x + (size_t)tok * Dm))[threadIdx.x];
    __half* row = g_Xg + (size_t)s * Dm + threadIdx.x * 4;
    *(__half2*)(row)     = __floats2half2_rn(v.x, v.y);
    *(__half2*)(row + 2) = __floats2half2_rn(v.z, v.w);
}

// ---------------- weight convert + transpose: [e][K][N] f32 -> [e][N][K] f16 ----------------
template <int K, int N, bool IS_W1>
__global__ void convert_w_kernel(const float* __restrict__ W) {
    __shared__ float tile[32][33];
    int e = blockIdx.z;
    int n0 = blockIdx.x * 32, k0 = blockIdx.y * 32;
    const float* src = W + (size_t)e * K * N;
    __half* dst = (IS_W1 ? g_W1h : g_W2h) + (size_t)e * K * N;
    int tx = threadIdx.x, ty = threadIdx.y;   // 32 x 8
    #pragma unroll
    for (int j = 0; j < 4; j++)
        tile[ty + j * 8][tx] = src[(size_t)(k0 + ty + j * 8) * N + n0 + tx];
    __syncthreads();
    #pragma unroll
    for (int j = 0; j < 4; j++)
        dst[(size_t)(n0 + ty + j * 8) * K + k0 + tx] = __float2half_rn(tile[tx][ty + j * 8]);
}

// ---------------- fp16 mma.sync grouped GEMM (ldmatrix, 3-stage pipeline) ----------------
#define MMA_F16(d, a, b)                                                      \
    asm volatile(                                                             \
        "mma.sync.aligned.m16n8k16.row.col.f32.f16.f16.f32 "                  \
        "{%0,%1,%2,%3}, {%4,%5,%6,%7}, {%8,%9}, {%0,%1,%2,%3};"               \
        : "+f"(d[0]), "+f"(d[1]), "+f"(d[2]), "+f"(d[3])                      \
        : "r"(a[0]), "r"(a[1]), "r"(a[2]), "r"(a[3]), "r"(b[0]), "r"(b[1]))

#define LDSM4(r0, r1, r2, r3, addr)                                           \
    asm volatile("ldmatrix.sync.aligned.m8n8.x4.shared.b16 {%0,%1,%2,%3}, [%4];" \
                 : "=r"(r0), "=r"(r1), "=r"(r2), "=r"(r3) : "r"(addr))

// PHASE1: A=g_Xg (K=Dm), B=g_W1h [e][F][D], O=g_H (bias+GELU, fp16)
// PHASE2: A=g_H  (K=Fm), B=g_W2h [e][D][F], O=atomicAdd into out (w*(v+b2))
template <bool PHASE1>
__global__ __launch_bounds__(256, 2) void gemm_kernel(const float* __restrict__ bias,
                                                      float* __restrict__ out) {
    const int K   = PHASE1 ? Dm : Fm;
    const int Nt  = PHASE1 ? Fm : Dm;
    const int KT  = K / BK;

    int e = blockIdx.z;
    int cnt = g_cnt[e];
    int mBase = blockIdx.y * BM;
    if (mBase >= cnt) return;
    int off = g_off[e];
    int nBase = blockIdx.x * BN;

    const __half* A  = (PHASE1 ? g_Xg : g_H) + (size_t)(off + mBase) * K;
    const __half* Bp = (PHASE1 ? g_W1h : g_W2h) + (size_t)e * (size_t)K * (size_t)Nt
                       + (size_t)nBase * K;   // rows = n, cols = k

    extern __shared__ __half dyn[];           // [3 stages A][3 stages B]

    int tid = threadIdx.x;
    int wid = tid >> 5, lane = tid & 31;
    int wm = wid & 3, wn = wid >> 2;      // 4 x 2 warp grid, 32(M) x 64(N) per warp
    int r = lane >> 2, c = lane & 3;

    float acc[2][8][4];
    #pragma unroll
    for (int mi = 0; mi < 2; mi++)
        #pragma unroll
        for (int ni = 0; ni < 8; ni++)
            #pragma unroll
            for (int q = 0; q < 4; q++) acc[mi][ni][q] = 0.f;

    unsigned smb = (unsigned)__cvta_generic_to_shared(&dyn[0]);

    // per-thread ldmatrix row addresses (byte offsets inside one stage)
    int q8 = lane >> 3, rr = lane & 7;
    unsigned offA = (unsigned)(((wm * 32 + (q8 & 1) * 8 + rr) * AST + (q8 >> 1) * 8) * 2);
    unsigned offB = (unsigned)(((wn * 64 + (q8 >> 1) * 8 + rr) * BST + (q8 & 1) * 8) * 2);

    auto load_stage = [&](int ktIdx, int buf) {
        int k0 = ktIdx * BK;
        unsigned asx = smb + (unsigned)buf * (STAGE_H * 2);
        unsigned bsx = smb + (unsigned)(3 + buf) * (STAGE_H * 2);
        #pragma unroll
        for (int i = 0; i < 2; i++) {
            int ch = tid + i * 256;
            int row = ch >> 2, kc = (ch & 3) * 8;
            const __half* src = A + (size_t)row * K + k0 + kc;
            unsigned dst = asx + (unsigned)(row * AST + kc) * 2u;
            asm volatile("cp.async.cg.shared.global [%0], [%1], 16;" :: "r"(dst), "l"(src));
        }
        #pragma unroll
        for (int i = 0; i < 2; i++) {
            int ch = tid + i * 256;
            int row = ch >> 2, kc = (ch & 3) * 8;
            const __half* src = Bp + (size_t)row * K + k0 + kc;
            unsigned dst = bsx + (unsigned)(row * BST + kc) * 2u;
            asm volatile("cp.async.cg.shared.global [%0], [%1], 16;" :: "r"(dst), "l"(src));
        }
        asm volatile("cp.async.commit_group;");
    };

    load_stage(0, 0);
    load_stage(1, 1);

    int cur = 0;
    for (int kt = 0; kt < KT; ++kt) {
        if (kt + 1 < KT) asm volatile("cp.async.wait_group 1;");
        else             asm volatile("cp.async.wait_group 0;");
        __syncthreads();
        if (kt + 2 < KT) {
            int nb = cur + 2; if (nb >= 3) nb -= 3;
            load_stage(kt + 2, nb);
        }

        unsigned aS = smb + (unsigned)cur * (STAGE_H * 2) + offA;
        unsigned bS = smb + (unsigned)(3 + cur) * (STAGE_H * 2) + offB;

        #pragma unroll
        for (int ks = 0; ks < 2; ++ks) {
            unsigned kkb = (unsigned)(ks * 16 * 2);
            unsigned a[2][4];
            LDSM4(a[0][0], a[0][1], a[0][2], a[0][3], aS + kkb);
            LDSM4(a[1][0], a[1][1], a[1][2], a[1][3], aS + kkb + 16u * AST * 2u);
            unsigned b[8][2];
            #pragma unroll
            for (int g = 0; g < 4; ++g) {
                LDSM4(b[2 * g][0], b[2 * g][1], b[2 * g + 1][0], b[2 * g + 1][1],
                      bS + kkb + (unsigned)g * 16u * BST * 2u);
            }
            #pragma unroll
            for (int mi = 0; mi < 2; ++mi)
                #pragma unroll
                for (int ni = 0; ni < 8; ++ni)
                    MMA_F16(acc[mi][ni], a[mi], b[ni]);
        }
        ++cur; if (cur == 3) cur = 0;
    }

    // ---- epilogue ----
    #pragma unroll
    for (int mi = 0; mi < 2; ++mi) {
        #pragma unroll
        for (int hh = 0; hh < 2; ++hh) {
            int m = wm * 32 + mi * 16 + r + hh * 8;
            if (mBase + m < cnt) {
                int slot = off + mBase + m;
                if (PHASE1) {
                    #pragma unroll
                    for (int ni = 0; ni < 8; ++ni) {
                        int col = wn * 64 + ni * 8 + 2 * c;
                        float v0 = acc[mi][ni][hh * 2 + 0];
                        float v1 = acc[mi][ni][hh * 2 + 1];
                        v0 += bias[(size_t)e * Fm + nBase + col];
                        v1 += bias[(size_t)e * Fm + nBase + col + 1];
                        v0 = 0.5f * v0 * (1.0f + erff(v0 * 0.70710678118654752440f));
                        v1 = 0.5f * v1 * (1.0f + erff(v1 * 0.70710678118654752440f));
                        *(__half2*)(g_H + (size_t)slot * Fm + nBase + col) = __floats2half2_rn(v0, v1);
                    }
                } else {
                    int tok = g_tokid[slot];
                    float w = g_wt[slot];
                    float* orow = out + (size_t)tok * Dm + nBase;
                    const float* b2row = bias + (size_t)e * Dm + nBase;
                    #pragma unroll
                    for (int ni = 0; ni < 8; ++ni) {
                        int col = wn * 64 + ni * 8 + 2 * c;
                        float v0 = acc[mi][ni][hh * 2 + 0] + b2row[col];
                        float v1 = acc[mi][ni][hh * 2 + 1] + b2row[col + 1];
                        atomicAdd(&orow[col],     w * v0);
                        atomicAdd(&orow[col + 1], w * v1);
                    }
                }
            }
        }
    }
}

extern "C" void kernel_launch(void* const* d_in, const int* in_sizes, int n_in,
                              void* d_out, int out_size) {
    const float* x  = (const float*)d_in[0];
    const float* Wr = (const float*)d_in[1];
    const float* br = (const float*)d_in[2];
    const float* W1 = (const float*)d_in[3];
    const float* b1 = (const float*)d_in[4];
    const float* W2 = (const float*)d_in[5];
    const float* b2 = (const float*)d_in[6];
    float* out = (float*)d_out;

    cudaFuncSetAttribute(gemm_kernel<true>,  cudaFuncAttributeMaxDynamicSharedMemorySize, SMEM_DYN);
    cudaFuncSetAttribute(gemm_kernel<false>, cudaFuncAttributeMaxDynamicSharedMemorySize, SMEM_DYN);

    zero_kernel<<<(Tm * Dm / 4) / 256, 256>>>(out);
    route_kernel<<<Tm, 256>>>(x, Wr, br);
    scan_kernel<<<1, 1>>>();
    scatter_kernel<<<(Tm + 255) / 256, 256>>>();
    gather_kernel<<<MAXP, 256>>>(x);

    dim3 cb(32, 8);
    convert_w_kernel<Dm, Fm, true ><<<dim3(Fm / 32, Dm / 32, Em), cb>>>(W1);
    convert_w_kernel<Fm, Dm, false><<<dim3(Dm / 32, Fm / 32, Em), cb>>>(W2);

    dim3 g1(Fm / BN, Tm / BM, Em);
    gemm_kernel<true><<<g1, 256, SMEM_DYN>>>(b1, nullptr);
    dim3 g2(Dm / BN, Tm / BM, Em);
    gemm_kernel<false><<<g2, 256, SMEM_DYN>>>(b2, out);
}

// round 10
// speedup vs baseline: 1.0221x; 1.0221x over previous
#include <cuda_runtime.h>
#include <cuda_fp16.h>
#include <cstdint>
#include <stdint.h>
#include <math.h>

#define Dm 1024
#define Fm 4096
#define Em 8
#define Tm 4096
#define MAXP (2 * Tm)
#define PADR 128

#define BM 128
#define BN 128
#define BK 32
#define AST (BK + 8)   // 40 halfs = 80B rows -> conflict-free ldmatrix, 16B-aligned
#define BST (BK + 8)

// ---- scratch (device globals; allocation is forbidden) ----
__device__ __half g_W1h[(size_t)Em * Fm * Dm];      // W1 transposed fp16: [e][f][d]
__device__ __half g_W2h[(size_t)Em * Dm * Fm];      // W2 transposed fp16: [e][d][f]
__device__ __half g_Xg[(size_t)(MAXP + PADR) * Dm]; // gathered tokens fp16
__device__ __half g_H [(size_t)(MAXP + PADR) * Fm]; // GELU activations fp16
__device__ float  g_Y [(size_t)(MAXP + PADR) * Dm]; // expert outputs fp32
__device__ int   g_cnt[Em];
__device__ int   g_off[Em];
__device__ int   g_fill[Em];
__device__ int   g_tokid[MAXP];
__device__ int   g_te[Tm];            // e0 | e1<<8
__device__ int   g_tslot[2 * Tm];     // slot of (token, k)
__device__ float g_tw[2 * Tm];        // routing weights

// ---------------- init counters ----------------
__global__ void init_kernel() {
    if (threadIdx.x < Em) g_cnt[threadIdx.x] = 0;
}

// ---------------- router: logits -> top2 -> softmax ----------------
__global__ void route_kernel(const float* __restrict__ x,
                             const float* __restrict__ Wr,
                             const float* __restrict__ br) {
    int t = blockIdx.x;
    __shared__ float xs[Dm];
    __shared__ float logits[Em];
    for (int i = threadIdx.x; i < Dm; i += blockDim.x) xs[i] = x[(size_t)t * Dm + i];
    __syncthreads();
    int warp = threadIdx.x >> 5, lane = threadIdx.x & 31;
    if (warp < Em) {
        float s = 0.f;
        for (int d = lane; d < Dm; d += 32) s += xs[d] * Wr[d * Em + warp];
        #pragma unroll
        for (int o = 16; o; o >>= 1) s += __shfl_xor_sync(0xffffffffu, s, o);
        if (lane == 0) logits[warp] = s + br[warp];
    }
    __syncthreads();
    if (threadIdx.x == 0) {
        int i0 = 0; float v0 = logits[0];
        #pragma unroll
        for (int e = 1; e < Em; e++) if (logits[e] > v0) { v0 = logits[e]; i0 = e; }
        int i1 = -1; float v1 = -1e30f;
        #pragma unroll
        for (int e = 0; e < Em; e++) if (e != i0 && logits[e] > v1) { v1 = logits[e]; i1 = e; }
        float e1 = expf(v1 - v0);
        float inv = 1.0f / (1.0f + e1);
        atomicAdd(&g_cnt[i0], 1);
        atomicAdd(&g_cnt[i1], 1);
        g_te[t] = i0 | (i1 << 8);
        g_tw[2 * t]     = inv;
        g_tw[2 * t + 1] = e1 * inv;
    }
}

// ---------------- tiny exclusive scan over 8 counts ----------------
__global__ void scan_kernel() {
    int o = 0;
    for (int e = 0; e < Em; e++) { g_off[e] = o; g_fill[e] = o; o += g_cnt[e]; }
}

// ---------------- scatter token ids into compact per-expert slots ----------------
__global__ void scatter_kernel() {
    int t = blockIdx.x * blockDim.x + threadIdx.x;
    if (t >= Tm) return;
    int p = g_te[t];
    int e0 = p & 255, e1 = p >> 8;
    int s0 = atomicAdd(&g_fill[e0], 1);
    g_tokid[s0] = t; g_tslot[2 * t] = s0;
    int s1 = atomicAdd(&g_fill[e1], 1);
    g_tokid[s1] = t; g_tslot[2 * t + 1] = s1;
}

// ---------------- gather tokens into compact fp16 rows ----------------
__global__ void gather_kernel(const float* __restrict__ x) {
    int s = blockIdx.x;
    int tok = g_tokid[s];
    float4 v = ((const float4*)(x + (size_t)tok * Dm))[threadIdx.x];
    __half* row = g_Xg + (size_t)s * Dm + threadIdx.x * 4;
    *(__half2*)(row)     = __floats2half2_rn(v.x, v.y);
    *(__half2*)(row + 2) = __floats2half2_rn(v.z, v.w);
}

// ---------------- weight convert + transpose: [e][K][N] f32 -> [e][N][K] f16 ----------------
template <int K, int N, bool IS_W1>
__global__ void convert_w_kernel(const float* __restrict__ W) {
    __shared__ float tile[32][33];
    int e = blockIdx.z;
    int n0 = blockIdx.x * 32, k0 = blockIdx.y * 32;
    const float* src = W + (size_t)e * K * N;
    __half* dst = (IS_W1 ? g_W1h : g_W2h) + (size_t)e * K * N;
    int tx = threadIdx.x, ty = threadIdx.y;   // 32 x 8
    #pragma unroll
    for (int j = 0; j < 4; j++)
        tile[ty + j * 8][tx] = src[(size_t)(k0 + ty + j * 8) * N + n0 + tx];
    __syncthreads();
    #pragma unroll
    for (int j = 0; j < 4; j++)
        dst[(size_t)(n0 + ty + j * 8) * K + k0 + tx] = __float2half_rn(tile[tx][ty + j * 8]);
}

// ---------------- fp16 mma.sync grouped GEMM (ldmatrix frag loads) ----------------
#define MMA_F16(d, a, b)                                                      \
    asm volatile(                                                             \
        "mma.sync.aligned.m16n8k16.row.col.f32.f16.f16.f32 "                  \
        "{%0,%1,%2,%3}, {%4,%5,%6,%7}, {%8,%9}, {%0,%1,%2,%3};"               \
        : "+f"(d[0]), "+f"(d[1]), "+f"(d[2]), "+f"(d[3])                      \
        : "r"(a[0]), "r"(a[1]), "r"(a[2]), "r"(a[3]), "r"(b[0]), "r"(b[1]))

#define LDSM4(r0, r1, r2, r3, addr)                                           \
    asm volatile("ldmatrix.sync.aligned.m8n8.x4.shared.b16 {%0,%1,%2,%3}, [%4];" \
                 : "=r"(r0), "=r"(r1), "=r"(r2), "=r"(r3) : "r"(addr))

// PHASE1: A=g_Xg (K=Dm), B=g_W1h [e][F][D], O=g_H (bias+GELU, fp16)
// PHASE2: A=g_H  (K=Fm), B=g_W2h [e][D][F], O=g_Y (raw fp32)
template <bool PHASE1>
__global__ __launch_bounds__(256, 2) void gemm_kernel(const float* __restrict__ bias) {
    const int K   = PHASE1 ? Dm : Fm;
    const int Nt  = PHASE1 ? Fm : Dm;
    const int KT  = K / BK;

    int e = blockIdx.z;
    int cnt = g_cnt[e];
    int mBase = blockIdx.y * BM;
    if (mBase >= cnt) return;
    int off = g_off[e];
    int nBase = blockIdx.x * BN;

    const __half* A  = (PHASE1 ? g_Xg : g_H) + (size_t)(off + mBase) * K;
    const __half* Bp = (PHASE1 ? g_W1h : g_W2h) + (size_t)e * (size_t)K * (size_t)Nt
                       + (size_t)nBase * K;   // rows = n, cols = k

    __shared__ __half As[2][BM][AST];
    __shared__ __half Bs[2][BN][BST];

    int tid = threadIdx.x;
    int wid = tid >> 5, lane = tid & 31;
    int wm = wid & 3, wn = wid >> 2;      // 4 x 2 warp grid, 32(M) x 64(N) per warp
    int r = lane >> 2, c = lane & 3;

    float acc[2][8][4];
    #pragma unroll
    for (int mi = 0; mi < 2; mi++)
        #pragma unroll
        for (int ni = 0; ni < 8; ni++)
            #pragma unroll
            for (int q = 0; q < 4; q++) acc[mi][ni][q] = 0.f;

    unsigned asb = (unsigned)__cvta_generic_to_shared(&As[0][0][0]);
    unsigned bsb = (unsigned)__cvta_generic_to_shared(&Bs[0][0][0]);

    // per-thread ldmatrix row addresses (byte offsets inside one stage)
    int q8 = lane >> 3, rr = lane & 7;
    unsigned offA = (unsigned)(((wm * 32 + (q8 & 1) * 8 + rr) * AST + (q8 >> 1) * 8) * 2);
    unsigned offB = (unsigned)(((wn * 64 + (q8 >> 1) * 8 + rr) * BST + (q8 & 1) * 8) * 2);

    auto load_stage = [&](int ktIdx, int buf) {
        int k0 = ktIdx * BK;
        unsigned asx = asb + (unsigned)buf * (BM * AST * 2);
        unsigned bsx = bsb + (unsigned)buf * (BN * BST * 2);
        #pragma unroll
        for (int i = 0; i < 2; i++) {
            int ch = tid + i * 256;
            int row = ch >> 2, kc = (ch & 3) * 8;
            const __half* src = A + (size_t)row * K + k0 + kc;
            unsigned dst = asx + (unsigned)(row * AST + kc) * 2u;
            asm volatile("cp.async.cg.shared.global [%0], [%1], 16;" :: "r"(dst), "l"(src));
        }
        #pragma unroll
        for (int i = 0; i < 2; i++) {
            int ch = tid + i * 256;
            int row = ch >> 2, kc = (ch & 3) * 8;
            const __half* src = Bp + (size_t)row * K + k0 + kc;
            unsigned dst = bsx + (unsigned)(row * BST + kc) * 2u;
            asm volatile("cp.async.cg.shared.global [%0], [%1], 16;" :: "r"(dst), "l"(src));
        }
        asm volatile("cp.async.commit_group;");
    };

    load_stage(0, 0);

    for (int kt = 0; kt < KT; ++kt) {
        int cur = kt & 1;
        asm volatile("cp.async.wait_group 0;");
        __syncthreads();
        if (kt + 1 < KT) load_stage(kt + 1, cur ^ 1);

        unsigned aS = asb + (unsigned)cur * (BM * AST * 2) + offA;
        unsigned bS = bsb + (unsigned)cur * (BN * BST * 2) + offB;

        #pragma unroll
        for (int ks = 0; ks < 2; ++ks) {
            unsigned kkb = (unsigned)(ks * 16 * 2);   // byte offset of k-slice
            unsigned a[2][4];
            LDSM4(a[0][0], a[0][1], a[0][2], a[0][3], aS + kkb);
            LDSM4(a[1][0], a[1][1], a[1][2], a[1][3], aS + kkb + 16u * AST * 2u);
            unsigned b[8][2];
            #pragma unroll
            for (int g = 0; g < 4; ++g) {
                LDSM4(b[2 * g][0], b[2 * g][1], b[2 * g + 1][0], b[2 * g + 1][1],
                      bS + kkb + (unsigned)g * 16u * BST * 2u);
            }
            #pragma unroll
            for (int mi = 0; mi < 2; ++mi)
                #pragma unroll
                for (int ni = 0; ni < 8; ++ni)
                    MMA_F16(acc[mi][ni], a[mi], b[ni]);
        }
    }

    // ---- epilogue ----
    #pragma unroll
    for (int mi = 0; mi < 2; ++mi) {
        #pragma unroll
        for (int hh = 0; hh < 2; ++hh) {
            int m = wm * 32 + mi * 16 + r + hh * 8;
            if (mBase + m < cnt) {
                size_t slot = (size_t)(off + mBase + m);
                #pragma unroll
                for (int ni = 0; ni < 8; ++ni) {
                    int col = wn * 64 + ni * 8 + 2 * c;
                    float v0 = acc[mi][ni][hh * 2 + 0];
                    float v1 = acc[mi][ni][hh * 2 + 1];
                    if (PHASE1) {
                        v0 += bias[(size_t)e * Fm + nBase + col];
                        v1 += bias[(size_t)e * Fm + nBase + col + 1];
                        v0 = 0.5f * v0 * (1.0f + erff(v0 * 0.70710678118654752440f));
                        v1 = 0.5f * v1 * (1.0f + erff(v1 * 0.70710678118654752440f));
                        *(__half2*)(g_H + slot * Fm + nBase + col) = __floats2half2_rn(v0, v1);
                    } else {
                        *(float2*)(g_Y + slot * Dm + nBase + col) = make_float2(v0, v1);
                    }
                }
            }
        }
    }
}

// ---------------- combine: out[t] = sum_k w_k * (Y[slot_k] + b2[e_k]) ----------------
__global__ void combine_kernel(float* __restrict__ out,
                               const float* __restrict__ b2) {
    int t = blockIdx.x;
    int p = g_te[t];
    int e0 = p & 255, e1 = p >> 8;
    float w0 = g_tw[2 * t], w1 = g_tw[2 * t + 1];
    int s0 = g_tslot[2 * t], s1 = g_tslot[2 * t + 1];
    int d = threadIdx.x;
    float4 y0 = ((const float4*)(g_Y + (size_t)s0 * Dm))[d];
    float4 y1 = ((const float4*)(g_Y + (size_t)s1 * Dm))[d];
    float4 c0 = ((const float4*)(b2 + (size_t)e0 * Dm))[d];
    float4 c1 = ((const float4*)(b2 + (size_t)e1 * Dm))[d];
    float4 o;
    o.x = w0 * (y0.x + c0.x) + w1 * (y1.x + c1.x);
    o.y = w0 * (y0.y + c0.y) + w1 * (y1.y + c1.y);
    o.z = w0 * (y0.z + c0.z) + w1 * (y1.z + c1.z);
    o.w = w0 * (y0.w + c0.w) + w1 * (y1.w + c1.w);
    ((float4*)(out + (size_t)t * Dm))[d] = o;
}

extern "C" void kernel_launch(void* const* d_in, const int* in_sizes, int n_in,
                              void* d_out, int out_size) {
    const float* x  = (const float*)d_in[0];
    const float* Wr = (const float*)d_in[1];
    const float* br = (const float*)d_in[2];
    const float* W1 = (const float*)d_in[3];
    const float* b1 = (const float*)d_in[4];
    const float* W2 = (const float*)d_in[5];
    const float* b2 = (const float*)d_in[6];
    float* out = (float*)d_out;

    // Side stream + events for overlap; created once on the first (uncaptured)
    // call, reused on the capture call. Event fork/join edges are captured
    // into the graph and preserve cross-stream dependencies.
    static cudaStream_t sW = nullptr;
    static cudaEvent_t evFork = nullptr, evW1 = nullptr, evW2 = nullptr;
    static bool streamOk = false;
    if (!sW) {
        streamOk =
            cudaStreamCreateWithFlags(&sW, cudaStreamNonBlocking) == cudaSuccess &&
            cudaEventCreateWithFlags(&evFork, cudaEventDisableTiming) == cudaSuccess &&
            cudaEventCreateWithFlags(&evW1,   cudaEventDisableTiming) == cudaSuccess &&
            cudaEventCreateWithFlags(&evW2,   cudaEventDisableTiming) == cudaSuccess;
    }

    dim3 cb(32, 8);
    dim3 gW1(Fm / 32, Dm / 32, Em);
    dim3 gW2(Dm / 32, Fm / 32, Em);

    if (streamOk) {
        // fork: converts run on sW, concurrent with the router chain
        cudaEventRecord(evFork, 0);
        cudaStreamWaitEvent(sW, evFork, 0);
        convert_w_kernel<Dm, Fm, true ><<<gW1, cb, 0, sW>>>(W1);
        cudaEventRecord(evW1, sW);
        convert_w_kernel<Fm, Dm, false><<<gW2, cb, 0, sW>>>(W2);
        cudaEventRecord(evW2, sW);
    } else {
        convert_w_kernel<Dm, Fm, true ><<<gW1, cb>>>(W1);
        convert_w_kernel<Fm, Dm, false><<<gW2, cb>>>(W2);
    }

    init_kernel<<<1, 32>>>();
    route_kernel<<<Tm, 256>>>(x, Wr, br);
    scan_kernel<<<1, 1>>>();
    scatter_kernel<<<(Tm + 255) / 256, 256>>>();
    gather_kernel<<<MAXP, 256>>>(x);

    if (streamOk) cudaStreamWaitEvent(0, evW1, 0);    // W1h ready
    dim3 g1(Fm / BN, Tm / BM, Em);
    gemm_kernel<true><<<g1, 256>>>(b1);

    if (streamOk) cudaStreamWaitEvent(0, evW2, 0);    // W2h ready
    dim3 g2(Dm / BN, Tm / BM, Em);
    gemm_kernel<false><<<g2, 256>>>(b2);

    combine_kernel<<<Tm, 256>>>(out, b2);
}

// round 11
// speedup vs baseline: 1.0418x; 1.0193x over previous
#include <cuda_runtime.h>
#include <cuda_fp16.h>
#include <cstdint>
#include <stdint.h>
#include <math.h>

#define Dm 1024
#define Fm 4096
#define Em 8
#define Tm 4096

#define BM 128
#define BN 128
#define BK 32
#define AST (BK + 8)   // 40 halfs = 80B rows -> conflict-free ldmatrix, 16B-aligned
#define BST (BK + 8)

// ---- scratch (device globals; allocation is forbidden) ----
// fixed per-expert regions: expert e owns rows [e*Tm, e*Tm + g_cnt[e])
__device__ __half g_W1h[(size_t)Em * Fm * Dm];      // W1 transposed fp16: [e][f][d]
__device__ __half g_W2h[(size_t)Em * Dm * Fm];      // W2 transposed fp16: [e][d][f]
__device__ __half g_Xg[(size_t)Em * Tm * Dm];       // gathered tokens fp16 (per-expert regions)
__device__ __half g_H [(size_t)Em * Tm * Fm];       // GELU activations fp16
__device__ float  g_Y [(size_t)Em * Tm * Dm];       // expert outputs fp32
__device__ int   g_cnt[Em];
__device__ int   g_te[Tm];            // e0 | e1<<8
__device__ int   g_tslot[2 * Tm];     // absolute slot of (token, k)
__device__ float g_tw[2 * Tm];        // routing weights

// ---------------- init counters ----------------
__global__ void init_kernel() {
    if (threadIdx.x < Em) g_cnt[threadIdx.x] = 0;
}

// ---- fused router: logits -> top2 -> softmax -> slot assign -> gather ----
__global__ __launch_bounds__(256) void route_gather_kernel(const float* __restrict__ x,
                                                           const float* __restrict__ Wr,
                                                           const float* __restrict__ br) {
    int t = blockIdx.x;
    __shared__ float xs[Dm];
    __shared__ float logits[Em];
    __shared__ int   sslot[2];

    // coalesced row load (float4)
    {
        float4 v = ((const float4*)(x + (size_t)t * Dm))[threadIdx.x];
        ((float4*)xs)[threadIdx.x] = v;
    }
    __syncthreads();

    int warp = threadIdx.x >> 5, lane = threadIdx.x & 31;
    {
        float s = 0.f;
        for (int d = lane; d < Dm; d += 32) s += xs[d] * Wr[d * Em + warp];
        #pragma unroll
        for (int o = 16; o; o >>= 1) s += __shfl_xor_sync(0xffffffffu, s, o);
        if (lane == 0) logits[warp] = s + br[warp];
    }
    __syncthreads();

    if (threadIdx.x == 0) {
        int i0 = 0; float v0 = logits[0];
        #pragma unroll
        for (int e = 1; e < Em; e++) if (logits[e] > v0) { v0 = logits[e]; i0 = e; }
        int i1 = -1; float v1 = -1e30f;
        #pragma unroll
        for (int e = 0; e < Em; e++) if (e != i0 && logits[e] > v1) { v1 = logits[e]; i1 = e; }
        float e1 = expf(v1 - v0);
        float inv = 1.0f / (1.0f + e1);
        int s0 = atomicAdd(&g_cnt[i0], 1);
        int s1 = atomicAdd(&g_cnt[i1], 1);
        int a0 = i0 * Tm + s0, a1 = i1 * Tm + s1;
        sslot[0] = a0; sslot[1] = a1;
        g_te[t] = i0 | (i1 << 8);
        g_tslot[2 * t] = a0; g_tslot[2 * t + 1] = a1;
        g_tw[2 * t] = inv;   g_tw[2 * t + 1] = e1 * inv;
    }
    __syncthreads();

    // write fp16 row into both expert slots (each thread: 4 values)
    int a0 = sslot[0], a1 = sslot[1];
    float4 v = ((const float4*)xs)[threadIdx.x];
    __half2 h0 = __floats2half2_rn(v.x, v.y);
    __half2 h1 = __floats2half2_rn(v.z, v.w);
    {
        __half* r0 = g_Xg + (size_t)a0 * Dm + threadIdx.x * 4;
        *(__half2*)(r0)     = h0;
        *(__half2*)(r0 + 2) = h1;
        __half* r1 = g_Xg + (size_t)a1 * Dm + threadIdx.x * 4;
        *(__half2*)(r1)     = h0;
        *(__half2*)(r1 + 2) = h1;
    }
}

// ---------------- weight convert + transpose: [e][K][N] f32 -> [e][N][K] f16 ----------------
template <int K, int N, bool IS_W1>
__global__ void convert_w_kernel(const float* __restrict__ W) {
    __shared__ float tile[32][33];
    int e = blockIdx.z;
    int n0 = blockIdx.x * 32, k0 = blockIdx.y * 32;
    const float* src = W + (size_t)e * K * N;
    __half* dst = (IS_W1 ? g_W1h : g_W2h) + (size_t)e * K * N;
    int tx = threadIdx.x, ty = threadIdx.y;   // 32 x 8
    #pragma unroll
    for (int j = 0; j < 4; j++)
        tile[ty + j * 8][tx] = src[(size_t)(k0 + ty + j * 8) * N + n0 + tx];
    __syncthreads();
    #pragma unroll
    for (int j = 0; j < 4; j++)
        dst[(size_t)(n0 + ty + j * 8) * K + k0 + tx] = __float2half_rn(tile[tx][ty + j * 8]);
}

// ---------------- fp16 mma.sync grouped GEMM (ldmatrix frag loads) ----------------
#define MMA_F16(d, a, b)                                                      \
    asm volatile(                                                             \
        "mma.sync.aligned.m16n8k16.row.col.f32.f16.f16.f32 "                  \
        "{%0,%1,%2,%3}, {%4,%5,%6,%7}, {%8,%9}, {%0,%1,%2,%3};"               \
        : "+f"(d[0]), "+f"(d[1]), "+f"(d[2]), "+f"(d[3])                      \
        : "r"(a[0]), "r"(a[1]), "r"(a[2]), "r"(a[3]), "r"(b[0]), "r"(b[1]))

#define LDSM4(r0, r1, r2, r3, addr)                                           \
    asm volatile("ldmatrix.sync.aligned.m8n8.x4.shared.b16 {%0,%1,%2,%3}, [%4];" \
                 : "=r"(r0), "=r"(r1), "=r"(r2), "=r"(r3) : "r"(addr))

// PHASE1: A=g_Xg (K=Dm), B=g_W1h [e][F][D], O=g_H (bias+GELU, fp16)
// PHASE2: A=g_H  (K=Fm), B=g_W2h [e][D][F], O=g_Y (raw fp32)
template <bool PHASE1>
__global__ __launch_bounds__(256, 2) void gemm_kernel(const float* __restrict__ bias) {
    const int K   = PHASE1 ? Dm : Fm;
    const int Nt  = PHASE1 ? Fm : Dm;
    const int KT  = K / BK;

    int e = blockIdx.z;
    int cnt = g_cnt[e];
    int mBase = blockIdx.y * BM;
    if (mBase >= cnt) return;
    int off = e * Tm;
    int nBase = blockIdx.x * BN;

    const __half* A  = (PHASE1 ? g_Xg : g_H) + (size_t)(off + mBase) * K;
    const __half* Bp = (PHASE1 ? g_W1h : g_W2h) + (size_t)e * (size_t)K * (size_t)Nt
                       + (size_t)nBase * K;   // rows = n, cols = k

    __shared__ __half As[2][BM][AST];
    __shared__ __half Bs[2][BN][BST];

    int tid = threadIdx.x;
    int wid = tid >> 5, lane = tid & 31;
    int wm = wid & 3, wn = wid >> 2;      // 4 x 2 warp grid, 32(M) x 64(N) per warp
    int r = lane >> 2, c = lane & 3;

    float acc[2][8][4];
    #pragma unroll
    for (int mi = 0; mi < 2; mi++)
        #pragma unroll
        for (int ni = 0; ni < 8; ni++)
            #pragma unroll
            for (int q = 0; q < 4; q++) acc[mi][ni][q] = 0.f;

    unsigned asb = (unsigned)__cvta_generic_to_shared(&As[0][0][0]);
    unsigned bsb = (unsigned)__cvta_generic_to_shared(&Bs[0][0][0]);

    int q8 = lane >> 3, rr = lane & 7;
    unsigned offA = (unsigned)(((wm * 32 + (q8 & 1) * 8 + rr) * AST + (q8 >> 1) * 8) * 2);
    unsigned offB = (unsigned)(((wn * 64 + (q8 >> 1) * 8 + rr) * BST + (q8 & 1) * 8) * 2);

    auto load_stage = [&](int ktIdx, int buf) {
        int k0 = ktIdx * BK;
        unsigned asx = asb + (unsigned)buf * (BM * AST * 2);
        unsigned bsx = bsb + (unsigned)buf * (BN * BST * 2);
        #pragma unroll
        for (int i = 0; i < 2; i++) {
            int ch = tid + i * 256;
            int row = ch >> 2, kc = (ch & 3) * 8;
            const __half* src = A + (size_t)row * K + k0 + kc;
            unsigned dst = asx + (unsigned)(row * AST + kc) * 2u;
            asm volatile("cp.async.cg.shared.global [%0], [%1], 16;" :: "r"(dst), "l"(src));
        }
        #pragma unroll
        for (int i = 0; i < 2; i++) {
            int ch = tid + i * 256;
            int row = ch >> 2, kc = (ch & 3) * 8;
            const __half* src = Bp + (size_t)row * K + k0 + kc;
            unsigned dst = bsx + (unsigned)(row * BST + kc) * 2u;
            asm volatile("cp.async.cg.shared.global [%0], [%1], 16;" :: "r"(dst), "l"(src));
        }
        asm volatile("cp.async.commit_group;");
    };

    load_stage(0, 0);

    for (int kt = 0; kt < KT; ++kt) {
        int cur = kt & 1;
        asm volatile("cp.async.wait_group 0;");
        __syncthreads();
        if (kt + 1 < KT) load_stage(kt + 1, cur ^ 1);

        unsigned aS = asb + (unsigned)cur * (BM * AST * 2) + offA;
        unsigned bS = bsb + (unsigned)cur * (BN * BST * 2) + offB;

        #pragma unroll
        for (int ks = 0; ks < 2; ++ks) {
            unsigned kkb = (unsigned)(ks * 16 * 2);
            unsigned a[2][4];
            LDSM4(a[0][0], a[0][1], a[0][2], a[0][3], aS + kkb);
            LDSM4(a[1][0], a[1][1], a[1][2], a[1][3], aS + kkb + 16u * AST * 2u);
            unsigned b[8][2];
            #pragma unroll
            for (int g = 0; g < 4; ++g) {
                LDSM4(b[2 * g][0], b[2 * g][1], b[2 * g + 1][0], b[2 * g + 1][1],
                      bS + kkb + (unsigned)g * 16u * BST * 2u);
            }
            #pragma unroll
            for (int mi = 0; mi < 2; ++mi)
                #pragma unroll
                for (int ni = 0; ni < 8; ++ni)
                    MMA_F16(acc[mi][ni], a[mi], b[ni]);
        }
    }

    // ---- epilogue ----
    #pragma unroll
    for (int mi = 0; mi < 2; ++mi) {
        #pragma unroll
        for (int hh = 0; hh < 2; ++hh) {
            int m = wm * 32 + mi * 16 + r + hh * 8;
            if (mBase + m < cnt) {
                size_t slot = (size_t)(off + mBase + m);
                #pragma unroll
                for (int ni = 0; ni < 8; ++ni) {
                    int col = wn * 64 + ni * 8 + 2 * c;
                    float v0 = acc[mi][ni][hh * 2 + 0];
                    float v1 = acc[mi][ni][hh * 2 + 1];
                    if (PHASE1) {
                        v0 += bias[(size_t)e * Fm + nBase + col];
                        v1 += bias[(size_t)e * Fm + nBase + col + 1];
                        v0 = 0.5f * v0 * (1.0f + erff(v0 * 0.70710678118654752440f));
                        v1 = 0.5f * v1 * (1.0f + erff(v1 * 0.70710678118654752440f));
                        *(__half2*)(g_H + slot * Fm + nBase + col) = __floats2half2_rn(v0, v1);
                    } else {
                        *(float2*)(g_Y + slot * Dm + nBase + col) = make_float2(v0, v1);
                    }
                }
            }
        }
    }
}

// ---------------- combine: out[t] = sum_k w_k * (Y[slot_k] + b2[e_k]) ----------------
__global__ void combine_kernel(float* __restrict__ out,
                               const float* __restrict__ b2) {
    int t = blockIdx.x;
    int p = g_te[t];
    int e0 = p & 255, e1 = p >> 8;
    float w0 = g_tw[2 * t], w1 = g_tw[2 * t + 1];
    int s0 = g_tslot[2 * t], s1 = g_tslot[2 * t + 1];
    int d = threadIdx.x;
    float4 y0 = ((const float4*)(g_Y + (size_t)s0 * Dm))[d];
    float4 y1 = ((const float4*)(g_Y + (size_t)s1 * Dm))[d];
    float4 c0 = ((const float4*)(b2 + (size_t)e0 * Dm))[d];
    float4 c1 = ((const float4*)(b2 + (size_t)e1 * Dm))[d];
    float4 o;
    o.x = w0 * (y0.x + c0.x) + w1 * (y1.x + c1.x);
    o.y = w0 * (y0.y + c0.y) + w1 * (y1.y + c1.y);
    o.z = w0 * (y0.z + c0.z) + w1 * (y1.z + c1.z);
    o.w = w0 * (y0.w + c0.w) + w1 * (y1.w + c1.w);
    ((float4*)(out + (size_t)t * Dm))[d] = o;
}

extern "C" void kernel_launch(void* const* d_in, const int* in_sizes, int n_in,
                              void* d_out, int out_size) {
    const float* x  = (const float*)d_in[0];
    const float* Wr = (const float*)d_in[1];
    const float* br = (const float*)d_in[2];
    const float* W1 = (const float*)d_in[3];
    const float* b1 = (const float*)d_in[4];
    const float* W2 = (const float*)d_in[5];
    const float* b2 = (const float*)d_in[6];
    float* out = (float*)d_out;

    // Side stream + events (created once on first, uncaptured, call).
    static cudaStream_t sW = nullptr;
    static cudaEvent_t evFork = nullptr, evW1 = nullptr, evW2 = nullptr;
    static bool streamOk = false;
    if (!sW) {
        streamOk =
            cudaStreamCreateWithFlags(&sW, cudaStreamNonBlocking) == cudaSuccess &&
            cudaEventCreateWithFlags(&evFork, cudaEventDisableTiming) == cudaSuccess &&
            cudaEventCreateWithFlags(&evW1,   cudaEventDisableTiming) == cudaSuccess &&
            cudaEventCreateWithFlags(&evW2,   cudaEventDisableTiming) == cudaSuccess;
    }

    dim3 cb(32, 8);
    dim3 gW1(Fm / 32, Dm / 32, Em);
    dim3 gW2(Dm / 32, Fm / 32, Em);

    if (streamOk) {
        cudaEventRecord(evFork, 0);
        cudaStreamWaitEvent(sW, evFork, 0);
        convert_w_kernel<Dm, Fm, true ><<<gW1, cb, 0, sW>>>(W1);
        cudaEventRecord(evW1, sW);
        convert_w_kernel<Fm, Dm, false><<<gW2, cb, 0, sW>>>(W2);
        cudaEventRecord(evW2, sW);
    } else {
        convert_w_kernel<Dm, Fm, true ><<<gW1, cb>>>(W1);
        convert_w_kernel<Fm, Dm, false><<<gW2, cb>>>(W2);
    }

    init_kernel<<<1, 32>>>();
    route_gather_kernel<<<Tm, 256>>>(x, Wr, br);

    if (streamOk) cudaStreamWaitEvent(0, evW1, 0);    // W1h ready
    dim3 g1(Fm / BN, Tm / BM, Em);
    gemm_kernel<true><<<g1, 256>>>(b1);

    if (streamOk) cudaStreamWaitEvent(0, evW2, 0);    // W2h ready
    dim3 g2(Dm / BN, Tm / BM, Em);
    gemm_kernel<false><<<g2, 256>>>(b2);

    combine_kernel<<<Tm, 256>>>(out, b2);
}

// round 13
// speedup vs baseline: 1.0424x; 1.0006x over previous
#include <cuda_runtime.h>
#include <cuda_fp16.h>
#include <cstdint>
#include <stdint.h>
#include <math.h>

#define Dm 1024
#define Fm 4096
#define Em 8
#define Tm 4096

#define BM 128
#define BN 128
#define BK 32
#define AST (BK + 8)   // 40 halfs = 80B rows -> conflict-free ldmatrix, 16B-aligned
#define BST (BK + 8)

// ---- scratch (device globals; allocation is forbidden) ----
// fixed per-expert regions: expert e owns rows [e*Tm, e*Tm + g_cnt[e])
__device__ __half g_W1h[(size_t)Em * Fm * Dm];      // W1 transposed fp16: [e][f][d]
__device__ __half g_W2h[(size_t)Em * Dm * Fm];      // W2 transposed fp16: [e][d][f]
__device__ __half g_Xg[(size_t)Em * Tm * Dm];       // gathered tokens fp16 (per-expert regions)
__device__ __half g_H [(size_t)Em * Tm * Fm];       // GELU activations fp16
__device__ float  g_Y [(size_t)Em * Tm * Dm];       // expert outputs fp32
__device__ int   g_cnt[Em];
__device__ int   g_te[Tm];            // e0 | e1<<8
__device__ int   g_tslot[2 * Tm];     // absolute slot of (token, k)
__device__ float g_tw[2 * Tm];        // routing weights

// ---------------- init counters ----------------
__global__ void init_kernel() {
    if (threadIdx.x < Em) g_cnt[threadIdx.x] = 0;
}

// ---- fused router: logits (register-accumulated) -> top2 -> softmax -> gather ----
__global__ __launch_bounds__(256) void route_gather_kernel(const float* __restrict__ x,
                                                           const float* __restrict__ Wr,
                                                           const float* __restrict__ br) {
    int t = blockIdx.x;
    int tid = threadIdx.x;
    __shared__ __align__(16) float xrow[Dm];   // MUST be 16B-aligned for float4 access
    __shared__ float red[8][Em];               // per-warp partial logits
    __shared__ float logits[Em];
    __shared__ int   sslot[2];

    // each thread owns 4 consecutive d's: coalesced float4 of x
    float4 xv = ((const float4*)(x + (size_t)t * Dm))[tid];
    ((float4*)xrow)[tid] = xv;

    // accumulate all 8 experts in registers; Wr row d = 8 floats (2 float4)
    float acc[Em];
    #pragma unroll
    for (int e = 0; e < Em; e++) acc[e] = 0.f;
    const float4* Wr4 = (const float4*)Wr;
    float xd[4] = {xv.x, xv.y, xv.z, xv.w};
    #pragma unroll
    for (int j = 0; j < 4; j++) {
        int d = tid * 4 + j;
        float4 w0 = Wr4[d * 2];
        float4 w1 = Wr4[d * 2 + 1];
        acc[0] += xd[j] * w0.x; acc[1] += xd[j] * w0.y;
        acc[2] += xd[j] * w0.z; acc[3] += xd[j] * w0.w;
        acc[4] += xd[j] * w1.x; acc[5] += xd[j] * w1.y;
        acc[6] += xd[j] * w1.z; acc[7] += xd[j] * w1.w;
    }
    // warp butterfly reduce each expert
    #pragma unroll
    for (int e = 0; e < Em; e++) {
        #pragma unroll
        for (int o = 16; o; o >>= 1) acc[e] += __shfl_xor_sync(0xffffffffu, acc[e], o);
    }
    int warp = tid >> 5, lane = tid & 31;
    if (lane == 0) {
        #pragma unroll
        for (int e = 0; e < Em; e++) red[warp][e] = acc[e];
    }
    __syncthreads();
    if (tid < Em) {
        float s = br[tid];
        #pragma unroll
        for (int w = 0; w < 8; w++) s += red[w][tid];
        logits[tid] = s;
    }
    __syncthreads();

    if (tid == 0) {
        int i0 = 0; float v0 = logits[0];
        #pragma unroll
        for (int e = 1; e < Em; e++) if (logits[e] > v0) { v0 = logits[e]; i0 = e; }
        int i1 = -1; float v1 = -1e30f;
        #pragma unroll
        for (int e = 0; e < Em; e++) if (e != i0 && logits[e] > v1) { v1 = logits[e]; i1 = e; }
        float e1 = expf(v1 - v0);
        float inv = 1.0f / (1.0f + e1);
        int s0 = atomicAdd(&g_cnt[i0], 1);
        int s1 = atomicAdd(&g_cnt[i1], 1);
        int a0 = i0 * Tm + s0, a1 = i1 * Tm + s1;
        sslot[0] = a0; sslot[1] = a1;
        g_te[t] = i0 | (i1 << 8);
        g_tslot[2 * t] = a0; g_tslot[2 * t + 1] = a1;
        g_tw[2 * t] = inv;   g_tw[2 * t + 1] = e1 * inv;
    }
    __syncthreads();

    // write fp16 row into both expert slots (each thread: 4 values)
    int a0 = sslot[0], a1 = sslot[1];
    float4 v = ((const float4*)xrow)[tid];
    __half2 h0 = __floats2half2_rn(v.x, v.y);
    __half2 h1 = __floats2half2_rn(v.z, v.w);
    {
        __half* r0 = g_Xg + (size_t)a0 * Dm + tid * 4;
        *(__half2*)(r0)     = h0;
        *(__half2*)(r0 + 2) = h1;
        __half* r1 = g_Xg + (size_t)a1 * Dm + tid * 4;
        *(__half2*)(r1)     = h0;
        *(__half2*)(r1 + 2) = h1;
    }
}

// ---------------- weight convert + transpose: [e][K][N] f32 -> [e][N][K] f16 ----------------
template <int K, int N, bool IS_W1>
__global__ void convert_w_kernel(const float* __restrict__ W) {
    __shared__ float tile[32][33];
    int e = blockIdx.z;
    int n0 = blockIdx.x * 32, k0 = blockIdx.y * 32;
    const float* src = W + (size_t)e * K * N;
    __half* dst = (IS_W1 ? g_W1h : g_W2h) + (size_t)e * K * N;
    int tx = threadIdx.x, ty = threadIdx.y;   // 32 x 8
    #pragma unroll
    for (int j = 0; j < 4; j++)
        tile[ty + j * 8][tx] = src[(size_t)(k0 + ty + j * 8) * N + n0 + tx];
    __syncthreads();
    #pragma unroll
    for (int j = 0; j < 4; j++)
        dst[(size_t)(n0 + ty + j * 8) * K + k0 + tx] = __float2half_rn(tile[tx][ty + j * 8]);
}

// ---------------- fp16 mma.sync grouped GEMM (ldmatrix frag loads) ----------------
#define MMA_F16(d, a, b)                                                      \
    asm volatile(                                                             \
        "mma.sync.aligned.m16n8k16.row.col.f32.f16.f16.f32 "                  \
        "{%0,%1,%2,%3}, {%4,%5,%6,%7}, {%8,%9}, {%0,%1,%2,%3};"               \
        : "+f"(d[0]), "+f"(d[1]), "+f"(d[2]), "+f"(d[3])                      \
        : "r"(a[0]), "r"(a[1]), "r"(a[2]), "r"(a[3]), "r"(b[0]), "r"(b[1]))

#define LDSM4(r0, r1, r2, r3, addr)                                           \
    asm volatile("ldmatrix.sync.aligned.m8n8.x4.shared.b16 {%0,%1,%2,%3}, [%4];" \
                 : "=r"(r0), "=r"(r1), "=r"(r2), "=r"(r3) : "r"(addr))

// PHASE1: A=g_Xg (K=Dm), B=g_W1h [e][F][D], O=g_H (bias+GELU, fp16)
// PHASE2: A=g_H  (K=Fm), B=g_W2h [e][D][F], O=g_Y (raw fp32)
template <bool PHASE1>
__global__ __launch_bounds__(256, 2) void gemm_kernel(const float* __restrict__ bias) {
    const int K   = PHASE1 ? Dm : Fm;
    const int Nt  = PHASE1 ? Fm : Dm;
    const int KT  = K / BK;

    int e = blockIdx.z;
    int cnt = g_cnt[e];
    int mBase = blockIdx.y * BM;
    if (mBase >= cnt) return;
    int off = e * Tm;
    int nBase = blockIdx.x * BN;

    const __half* A  = (PHASE1 ? g_Xg : g_H) + (size_t)(off + mBase) * K;
    const __half* Bp = (PHASE1 ? g_W1h : g_W2h) + (size_t)e * (size_t)K * (size_t)Nt
                       + (size_t)nBase * K;   // rows = n, cols = k

    __shared__ __half As[2][BM][AST];
    __shared__ __half Bs[2][BN][BST];

    int tid = threadIdx.x;
    int wid = tid >> 5, lane = tid & 31;
    int wm = wid & 3, wn = wid >> 2;      // 4 x 2 warp grid, 32(M) x 64(N) per warp
    int r = lane >> 2, c = lane & 3;

    float acc[2][8][4];
    #pragma unroll
    for (int mi = 0; mi < 2; mi++)
        #pragma unroll
        for (int ni = 0; ni < 8; ni++)
            #pragma unroll
            for (int q = 0; q < 4; q++) acc[mi][ni][q] = 0.f;

    unsigned asb = (unsigned)__cvta_generic_to_shared(&As[0][0][0]);
    unsigned bsb = (unsigned)__cvta_generic_to_shared(&Bs[0][0][0]);

    int q8 = lane >> 3, rr = lane & 7;
    unsigned offA = (unsigned)(((wm * 32 + (q8 & 1) * 8 + rr) * AST + (q8 >> 1) * 8) * 2);
    unsigned offB = (unsigned)(((wn * 64 + (q8 >> 1) * 8 + rr) * BST + (q8 & 1) * 8) * 2);

    auto load_stage = [&](int ktIdx, int buf) {
        int k0 = ktIdx * BK;
        unsigned asx = asb + (unsigned)buf * (BM * AST * 2);
        unsigned bsx = bsb + (unsigned)buf * (BN * BST * 2);
        #pragma unroll
        for (int i = 0; i < 2; i++) {
            int ch = tid + i * 256;
            int row = ch >> 2, kc = (ch & 3) * 8;
            const __half* src = A + (size_t)row * K + k0 + kc;
            unsigned dst = asx + (unsigned)(row * AST + kc) * 2u;
            asm volatile("cp.async.cg.shared.global [%0], [%1], 16;" :: "r"(dst), "l"(src));
        }
        #pragma unroll
        for (int i = 0; i < 2; i++) {
            int ch = tid + i * 256;
            int row = ch >> 2, kc = (ch & 3) * 8;
            const __half* src = Bp + (size_t)row * K + k0 + kc;
            unsigned dst = bsx + (unsigned)(row * BST + kc) * 2u;
            asm volatile("cp.async.cg.shared.global [%0], [%1], 16;" :: "r"(dst), "l"(src));
        }
        asm volatile("cp.async.commit_group;");
    };

    load_stage(0, 0);

    for (int kt = 0; kt < KT; ++kt) {
        int cur = kt & 1;
        asm volatile("cp.async.wait_group 0;");
        __syncthreads();
        if (kt + 1 < KT) load_stage(kt + 1, cur ^ 1);

        unsigned aS = asb + (unsigned)cur * (BM * AST * 2) + offA;
        unsigned bS = bsb + (unsigned)cur * (BN * BST * 2) + offB;

        #pragma unroll
        for (int ks = 0; ks < 2; ++ks) {
            unsigned kkb = (unsigned)(ks * 16 * 2);
            unsigned a[2][4];
            LDSM4(a[0][0], a[0][1], a[0][2], a[0][3], aS + kkb);
            LDSM4(a[1][0], a[1][1], a[1][2], a[1][3], aS + kkb + 16u * AST * 2u);
            unsigned b[8][2];
            #pragma unroll
            for (int g = 0; g < 4; ++g) {
                LDSM4(b[2 * g][0], b[2 * g][1], b[2 * g + 1][0], b[2 * g + 1][1],
                      bS + kkb + (unsigned)g * 16u * BST * 2u);
            }
            #pragma unroll
            for (int mi = 0; mi < 2; ++mi)
                #pragma unroll
                for (int ni = 0; ni < 8; ++ni)
                    MMA_F16(acc[mi][ni], a[mi], b[ni]);
        }
    }

    // ---- epilogue ----
    #pragma unroll
    for (int mi = 0; mi < 2; ++mi) {
        #pragma unroll
        for (int hh = 0; hh < 2; ++hh) {
            int m = wm * 32 + mi * 16 + r + hh * 8;
            if (mBase + m < cnt) {
                size_t slot = (size_t)(off + mBase + m);
                #pragma unroll
                for (int ni = 0; ni < 8; ++ni) {
                    int col = wn * 64 + ni * 8 + 2 * c;
                    float v0 = acc[mi][ni][hh * 2 + 0];
                    float v1 = acc[mi][ni][hh * 2 + 1];
                    if (PHASE1) {
                        v0 += bias[(size_t)e * Fm + nBase + col];
                        v1 += bias[(size_t)e * Fm + nBase + col + 1];
                        v0 = 0.5f * v0 * (1.0f + erff(v0 * 0.70710678118654752440f));
                        v1 = 0.5f * v1 * (1.0f + erff(v1 * 0.70710678118654752440f));
                        *(__half2*)(g_H + slot * Fm + nBase + col) = __floats2half2_rn(v0, v1);
                    } else {
                        *(float2*)(g_Y + slot * Dm + nBase + col) = make_float2(v0, v1);
                    }
                }
            }
        }
    }
}

// ---------------- combine: out[t] = sum_k w_k * (Y[slot_k] + b2[e_k]) ----------------
__global__ void combine_kernel(float* __restrict__ out,
                               const float* __restrict__ b2) {
    int t = blockIdx.x;
    int p = g_te[t];
    int e0 = p & 255, e1 = p >> 8;
    float w0 = g_tw[2 * t], w1 = g_tw[2 * t + 1];
    int s0 = g_tslot[2 * t], s1 = g_tslot[2 * t + 1];
    int d = threadIdx.x;
    float4 y0 = ((const float4*)(g_Y + (size_t)s0 * Dm))[d];
    float4 y1 = ((const float4*)(g_Y + (size_t)s1 * Dm))[d];
    float4 c0 = ((const float4*)(b2 + (size_t)e0 * Dm))[d];
    float4 c1 = ((const float4*)(b2 + (size_t)e1 * Dm))[d];
    float4 o;
    o.x = w0 * (y0.x + c0.x) + w1 * (y1.x + c1.x);
    o.y = w0 * (y0.y + c0.y) + w1 * (y1.y + c1.y);
    o.z = w0 * (y0.z + c0.z) + w1 * (y1.z + c1.z);
    o.w = w0 * (y0.w + c0.w) + w1 * (y1.w + c1.w);
    ((float4*)(out + (size_t)t * Dm))[d] = o;
}

extern "C" void kernel_launch(void* const* d_in, const int* in_sizes, int n_in,
                              void* d_out, int out_size) {
    const float* x  = (const float*)d_in[0];
    const float* Wr = (const float*)d_in[1];
    const float* br = (const float*)d_in[2];
    const float* W1 = (const float*)d_in[3];
    const float* b1 = (const float*)d_in[4];
    const float* W2 = (const float*)d_in[5];
    const float* b2 = (const float*)d_in[6];
    float* out = (float*)d_out;

    // Side stream + events (created once on first, uncaptured, call).
    static cudaStream_t sW = nullptr;
    static cudaEvent_t evFork = nullptr, evW1 = nullptr, evW2 = nullptr;
    static bool streamOk = false;
    if (!sW) {
        streamOk =
            cudaStreamCreateWithFlags(&sW, cudaStreamNonBlocking) == cudaSuccess &&
            cudaEventCreateWithFlags(&evFork, cudaEventDisableTiming) == cudaSuccess &&
            cudaEventCreateWithFlags(&evW1,   cudaEventDisableTiming) == cudaSuccess &&
            cudaEventCreateWithFlags(&evW2,   cudaEventDisableTiming) == cudaSuccess;
    }

    dim3 cb(32, 8);
    dim3 gW1(Fm / 32, Dm / 32, Em);
    dim3 gW2(Dm / 32, Fm / 32, Em);

    if (streamOk) {
        cudaEventRecord(evFork, 0);
        cudaStreamWaitEvent(sW, evFork, 0);
        convert_w_kernel<Dm, Fm, true ><<<gW1, cb, 0, sW>>>(W1);
        cudaEventRecord(evW1, sW);
        convert_w_kernel<Fm, Dm, false><<<gW2, cb, 0, sW>>>(W2);
        cudaEventRecord(evW2, sW);
    } else {
        convert_w_kernel<Dm, Fm, true ><<<gW1, cb>>>(W1);
        convert_w_kernel<Fm, Dm, false><<<gW2, cb>>>(W2);
    }

    init_kernel<<<1, 32>>>();
    route_gather_kernel<<<Tm, 256>>>(x, Wr, br);

    if (streamOk) cudaStreamWaitEvent(0, evW1, 0);    // W1h ready
    dim3 g1(Fm / BN, Tm / BM, Em);
    gemm_kernel<true><<<g1, 256>>>(b1);

    if (streamOk) cudaStreamWaitEvent(0, evW2, 0);    // W2h ready
    dim3 g2(Dm / BN, Tm / BM, Em);
    gemm_kernel<false><<<g2, 256>>>(b2);

    combine_kernel<<<Tm, 256>>>(out, b2);
}

// round 14
// speedup vs baseline: 1.0869x; 1.0427x over previous
#include <cuda_runtime.h>
#include <cuda_fp16.h>
#include <cstdint>
#include <stdint.h>
#include <math.h>

#define Dm 1024
#define Fm 4096
#define Em 8
#define Tm 4096

#define BM 128
#define BN 128
#define BK 32
#define AST (BK + 8)   // 40 halfs = 80B rows -> conflict-free ldmatrix, 16B-aligned
#define BST (BK + 8)

// ---- scratch (device globals; allocation is forbidden) ----
// fixed per-expert regions: expert e owns rows [e*Tm, e*Tm + g_cnt[e])
__device__ __half g_W1h[(size_t)Em * Fm * Dm];      // W1 transposed fp16: [e][f][d]
__device__ __half g_W2h[(size_t)Em * Dm * Fm];      // W2 transposed fp16: [e][d][f]
__device__ __half g_Xg[(size_t)Em * Tm * Dm];       // gathered tokens fp16 (per-expert regions)
__device__ __half g_H [(size_t)Em * Tm * Fm];       // GELU activations fp16
__device__ float  g_Y [(size_t)Em * Tm * Dm];       // expert outputs fp32
__device__ int   g_cnt[Em];
__device__ int   g_te[Tm];            // e0 | e1<<8
__device__ int   g_tslot[2 * Tm];     // absolute slot of (token, k)
__device__ float g_tw[2 * Tm];        // routing weights

// ---------------- init counters ----------------
__global__ void init_kernel() {
    if (threadIdx.x < Em) g_cnt[threadIdx.x] = 0;
}

// ---- fused router: coalesced Wr loads -> top2 -> softmax -> gather ----
// Wr viewed as 2048 float4; float4 idx covers d=idx>>1, experts (idx&1)*4..+3.
// Thread tid loads idx = tid + i*256 (fully coalesced); its parity is fixed,
// so it accumulates 4 experts over 8 d-values in registers.
__global__ __launch_bounds__(256) void route_gather_kernel(const float* __restrict__ x,
                                                           const float* __restrict__ Wr,
                                                           const float* __restrict__ br) {
    int t = blockIdx.x;
    int tid = threadIdx.x;
    __shared__ __align__(16) float xrow[Dm];
    __shared__ float red[8][2][4];             // [warp][parity][expert-in-group]
    __shared__ float logits[Em];
    __shared__ int   sslot[2];

    // coalesced float4 load of x row
    float4 xv = ((const float4*)(x + (size_t)t * Dm))[tid];
    ((float4*)xrow)[tid] = xv;
    __syncthreads();

    // coalesced Wr accumulate: 8 float4 loads per thread
    float acc[4] = {0.f, 0.f, 0.f, 0.f};
    const float4* Wr4 = (const float4*)Wr;
    #pragma unroll
    for (int i = 0; i < 8; i++) {
        int idx = tid + i * 256;               // 0..2047
        float4 w = Wr4[idx];
        float xd = xrow[idx >> 1];
        acc[0] += xd * w.x; acc[1] += xd * w.y;
        acc[2] += xd * w.z; acc[3] += xd * w.w;
    }
    // butterfly over bits 1..4: every lane ends with the sum over all lanes
    // of its own parity; lane 0 -> parity 0 (experts 0-3), lane 1 -> parity 1.
    #pragma unroll
    for (int o = 2; o <= 16; o <<= 1) {
        #pragma unroll
        for (int k = 0; k < 4; k++) acc[k] += __shfl_xor_sync(0xffffffffu, acc[k], o);
    }
    int warp = tid >> 5, lane = tid & 31;
    if (lane < 2) {
        #pragma unroll
        for (int k = 0; k < 4; k++) red[warp][lane][k] = acc[k];
    }
    __syncthreads();
    if (tid < Em) {
        int g = tid >> 2, k = tid & 3;
        float s = br[tid];
        #pragma unroll
        for (int w = 0; w < 8; w++) s += red[w][g][k];
        logits[tid] = s;
    }
    __syncthreads();

    if (tid == 0) {
        int i0 = 0; float v0 = logits[0];
        #pragma unroll
        for (int e = 1; e < Em; e++) if (logits[e] > v0) { v0 = logits[e]; i0 = e; }
        int i1 = -1; float v1 = -1e30f;
        #pragma unroll
        for (int e = 0; e < Em; e++) if (e != i0 && logits[e] > v1) { v1 = logits[e]; i1 = e; }
        float e1 = expf(v1 - v0);
        float inv = 1.0f / (1.0f + e1);
        int s0 = atomicAdd(&g_cnt[i0], 1);
        int s1 = atomicAdd(&g_cnt[i1], 1);
        int a0 = i0 * Tm + s0, a1 = i1 * Tm + s1;
        sslot[0] = a0; sslot[1] = a1;
        g_te[t] = i0 | (i1 << 8);
        g_tslot[2 * t] = a0; g_tslot[2 * t + 1] = a1;
        g_tw[2 * t] = inv;   g_tw[2 * t + 1] = e1 * inv;
    }
    __syncthreads();

    // write fp16 row into both expert slots (each thread: 4 values)
    int a0 = sslot[0], a1 = sslot[1];
    float4 v = ((const float4*)xrow)[tid];
    __half2 h0 = __floats2half2_rn(v.x, v.y);
    __half2 h1 = __floats2half2_rn(v.z, v.w);
    {
        __half* r0 = g_Xg + (size_t)a0 * Dm + tid * 4;
        *(__half2*)(r0)     = h0;
        *(__half2*)(r0 + 2) = h1;
        __half* r1 = g_Xg + (size_t)a1 * Dm + tid * 4;
        *(__half2*)(r1)     = h0;
        *(__half2*)(r1 + 2) = h1;
    }
}

// ---------------- weight convert + transpose: [e][K][N] f32 -> [e][N][K] f16 ----------------
template <int K, int N, bool IS_W1>
__global__ void convert_w_kernel(const float* __restrict__ W) {
    __shared__ float tile[32][33];
    int e = blockIdx.z;
    int n0 = blockIdx.x * 32, k0 = blockIdx.y * 32;
    const float* src = W + (size_t)e * K * N;
    __half* dst = (IS_W1 ? g_W1h : g_W2h) + (size_t)e * K * N;
    int tx = threadIdx.x, ty = threadIdx.y;   // 32 x 8
    #pragma unroll
    for (int j = 0; j < 4; j++)
        tile[ty + j * 8][tx] = src[(size_t)(k0 + ty + j * 8) * N + n0 + tx];
    __syncthreads();
    #pragma unroll
    for (int j = 0; j < 4; j++)
        dst[(size_t)(n0 + ty + j * 8) * K + k0 + tx] = __float2half_rn(tile[tx][ty + j * 8]);
}

// ---------------- fp16 mma.sync grouped GEMM (ldmatrix frag loads) ----------------
#define MMA_F16(d, a, b)                                                      \
    asm volatile(                                                             \
        "mma.sync.aligned.m16n8k16.row.col.f32.f16.f16.f32 "                  \
        "{%0,%1,%2,%3}, {%4,%5,%6,%7}, {%8,%9}, {%0,%1,%2,%3};"               \
        : "+f"(d[0]), "+f"(d[1]), "+f"(d[2]), "+f"(d[3])                      \
        : "r"(a[0]), "r"(a[1]), "r"(a[2]), "r"(a[3]), "r"(b[0]), "r"(b[1]))

#define LDSM4(r0, r1, r2, r3, addr)                                           \
    asm volatile("ldmatrix.sync.aligned.m8n8.x4.shared.b16 {%0,%1,%2,%3}, [%4];" \
                 : "=r"(r0), "=r"(r1), "=r"(r2), "=r"(r3) : "r"(addr))

// PHASE1: A=g_Xg (K=Dm), B=g_W1h [e][F][D], O=g_H (bias+GELU, fp16)
// PHASE2: A=g_H  (K=Fm), B=g_W2h [e][D][F], O=g_Y (raw fp32)
template <bool PHASE1>
__global__ __launch_bounds__(256, 2) void gemm_kernel(const float* __restrict__ bias) {
    const int K   = PHASE1 ? Dm : Fm;
    const int Nt  = PHASE1 ? Fm : Dm;
    const int KT  = K / BK;

    int e = blockIdx.z;
    int cnt = g_cnt[e];
    int mBase = blockIdx.y * BM;
    if (mBase >= cnt) return;
    int off = e * Tm;
    int nBase = blockIdx.x * BN;

    const __half* A  = (PHASE1 ? g_Xg : g_H) + (size_t)(off + mBase) * K;
    const __half* Bp = (PHASE1 ? g_W1h : g_W2h) + (size_t)e * (size_t)K * (size_t)Nt
                       + (size_t)nBase * K;   // rows = n, cols = k

    __shared__ __half As[2][BM][AST];
    __shared__ __half Bs[2][BN][BST];

    int tid = threadIdx.x;
    int wid = tid >> 5, lane = tid & 31;
    int wm = wid & 3, wn = wid >> 2;      // 4 x 2 warp grid, 32(M) x 64(N) per warp
    int r = lane >> 2, c = lane & 3;

    float acc[2][8][4];
    #pragma unroll
    for (int mi = 0; mi < 2; mi++)
        #pragma unroll
        for (int ni = 0; ni < 8; ni++)
            #pragma unroll
            for (int q = 0; q < 4; q++) acc[mi][ni][q] = 0.f;

    unsigned asb = (unsigned)__cvta_generic_to_shared(&As[0][0][0]);
    unsigned bsb = (unsigned)__cvta_generic_to_shared(&Bs[0][0][0]);

    int q8 = lane >> 3, rr = lane & 7;
    unsigned offA = (unsigned)(((wm * 32 + (q8 & 1) * 8 + rr) * AST + (q8 >> 1) * 8) * 2);
    unsigned offB = (unsigned)(((wn * 64 + (q8 >> 1) * 8 + rr) * BST + (q8 & 1) * 8) * 2);

    auto load_stage = [&](int ktIdx, int buf) {
        int k0 = ktIdx * BK;
        unsigned asx = asb + (unsigned)buf * (BM * AST * 2);
        unsigned bsx = bsb + (unsigned)buf * (BN * BST * 2);
        #pragma unroll
        for (int i = 0; i < 2; i++) {
            int ch = tid + i * 256;
            int row = ch >> 2, kc = (ch & 3) * 8;
            const __half* src = A + (size_t)row * K + k0 + kc;
            unsigned dst = asx + (unsigned)(row * AST + kc) * 2u;
            asm volatile("cp.async.cg.shared.global [%0], [%1], 16;" :: "r"(dst), "l"(src));
        }
        #pragma unroll
        for (int i = 0; i < 2; i++) {
            int ch = tid + i * 256;
            int row = ch >> 2, kc = (ch & 3) * 8;
            const __half* src = Bp + (size_t)row * K + k0 + kc;
            unsigned dst = bsx + (unsigned)(row * BST + kc) * 2u;
            asm volatile("cp.async.cg.shared.global [%0], [%1], 16;" :: "r"(dst), "l"(src));
        }
        asm volatile("cp.async.commit_group;");
    };

    load_stage(0, 0);

    for (int kt = 0; kt < KT; ++kt) {
        int cur = kt & 1;
        asm volatile("cp.async.wait_group 0;");
        __syncthreads();
        if (kt + 1 < KT) load_stage(kt + 1, cur ^ 1);

        unsigned aS = asb + (unsigned)cur * (BM * AST * 2) + offA;
        unsigned bS = bsb + (unsigned)cur * (BN * BST * 2) + offB;

        #pragma unroll
        for (int ks = 0; ks < 2; ++ks) {
            unsigned kkb = (unsigned)(ks * 16 * 2);
            unsigned a[2][4];
            LDSM4(a[0][0], a[0][1], a[0][2], a[0][3], aS + kkb);
            LDSM4(a[1][0], a[1][1], a[1][2], a[1][3], aS + kkb + 16u * AST * 2u);
            unsigned b[8][2];
            #pragma unroll
            for (int g = 0; g < 4; ++g) {
                LDSM4(b[2 * g][0], b[2 * g][1], b[2 * g + 1][0], b[2 * g + 1][1],
                      bS + kkb + (unsigned)g * 16u * BST * 2u);
            }
            #pragma unroll
            for (int mi = 0; mi < 2; ++mi)
                #pragma unroll
                for (int ni = 0; ni < 8; ++ni)
                    MMA_F16(acc[mi][ni], a[mi], b[ni]);
        }
    }

    // ---- epilogue ----
    #pragma unroll
    for (int mi = 0; mi < 2; ++mi) {
        #pragma unroll
        for (int hh = 0; hh < 2; ++hh) {
            int m = wm * 32 + mi * 16 + r + hh * 8;
            if (mBase + m < cnt) {
                size_t slot = (size_t)(off + mBase + m);
                #pragma unroll
                for (int ni = 0; ni < 8; ++ni) {
                    int col = wn * 64 + ni * 8 + 2 * c;
                    float v0 = acc[mi][ni][hh * 2 + 0];
                    float v1 = acc[mi][ni][hh * 2 + 1];
                    if (PHASE1) {
                        v0 += bias[(size_t)e * Fm + nBase + col];
                        v1 += bias[(size_t)e * Fm + nBase + col + 1];
                        v0 = 0.5f * v0 * (1.0f + erff(v0 * 0.70710678118654752440f));
                        v1 = 0.5f * v1 * (1.0f + erff(v1 * 0.70710678118654752440f));
                        *(__half2*)(g_H + slot * Fm + nBase + col) = __floats2half2_rn(v0, v1);
                    } else {
                        *(float2*)(g_Y + slot * Dm + nBase + col) = make_float2(v0, v1);
                    }
                }
            }
        }
    }
}

// ---------------- combine: out[t] = sum_k w_k * (Y[slot_k] + b2[e_k]) ----------------
__global__ void combine_kernel(float* __restrict__ out,
                               const float* __restrict__ b2) {
    int t = blockIdx.x;
    int p = g_te[t];
    int e0 = p & 255, e1 = p >> 8;
    float w0 = g_tw[2 * t], w1 = g_tw[2 * t + 1];
    int s0 = g_tslot[2 * t], s1 = g_tslot[2 * t + 1];
    int d = threadIdx.x;
    float4 y0 = ((const float4*)(g_Y + (size_t)s0 * Dm))[d];
    float4 y1 = ((const float4*)(g_Y + (size_t)s1 * Dm))[d];
    float4 c0 = ((const float4*)(b2 + (size_t)e0 * Dm))[d];
    float4 c1 = ((const float4*)(b2 + (size_t)e1 * Dm))[d];
    float4 o;
    o.x = w0 * (y0.x + c0.x) + w1 * (y1.x + c1.x);
    o.y = w0 * (y0.y + c0.y) + w1 * (y1.y + c1.y);
    o.z = w0 * (y0.z + c0.z) + w1 * (y1.z + c1.z);
    o.w = w0 * (y0.w + c0.w) + w1 * (y1.w + c1.w);
    ((float4*)(out + (size_t)t * Dm))[d] = o;
}

extern "C" void kernel_launch(void* const* d_in, const int* in_sizes, int n_in,
                              void* d_out, int out_size) {
    const float* x  = (const float*)d_in[0];
    const float* Wr = (const float*)d_in[1];
    const float* br = (const float*)d_in[2];
    const float* W1 = (const float*)d_in[3];
    const float* b1 = (const float*)d_in[4];
    const float* W2 = (const float*)d_in[5];
    const float* b2 = (const float*)d_in[6];
    float* out = (float*)d_out;

    // Side stream + events (created once on first, uncaptured, call).
    static cudaStream_t sW = nullptr;
    static cudaEvent_t evFork = nullptr, evW1 = nullptr, evW2 = nullptr;
    static bool streamOk = false;
    if (!sW) {
        streamOk =
            cudaStreamCreateWithFlags(&sW, cudaStreamNonBlocking) == cudaSuccess &&
            cudaEventCreateWithFlags(&evFork, cudaEventDisableTiming) == cudaSuccess &&
            cudaEventCreateWithFlags(&evW1,   cudaEventDisableTiming) == cudaSuccess &&
            cudaEventCreateWithFlags(&evW2,   cudaEventDisableTiming) == cudaSuccess;
    }

    dim3 cb(32, 8);
    dim3 gW1(Fm / 32, Dm / 32, Em);
    dim3 gW2(Dm / 32, Fm / 32, Em);

    if (streamOk) {
        cudaEventRecord(evFork, 0);
        cudaStreamWaitEvent(sW, evFork, 0);
        convert_w_kernel<Dm, Fm, true ><<<gW1, cb, 0, sW>>>(W1);
        cudaEventRecord(evW1, sW);
        convert_w_kernel<Fm, Dm, false><<<gW2, cb, 0, sW>>>(W2);
        cudaEventRecord(evW2, sW);
    } else {
        convert_w_kernel<Dm, Fm, true ><<<gW1, cb>>>(W1);
        convert_w_kernel<Fm, Dm, false><<<gW2, cb>>>(W2);
    }

    init_kernel<<<1, 32>>>();
    route_gather_kernel<<<Tm, 256>>>(x, Wr, br);

    if (streamOk) cudaStreamWaitEvent(0, evW1, 0);    // W1h ready
    dim3 g1(Fm / BN, Tm / BM, Em);
    gemm_kernel<true><<<g1, 256>>>(b1);

    if (streamOk) cudaStreamWaitEvent(0, evW2, 0);    // W2h ready
    dim3 g2(Dm / BN, Tm / BM, Em);
    gemm_kernel<false><<<g2, 256>>>(b2);

    combine_kernel<<<Tm, 256>>>(out, b2);
}

// round 15
// speedup vs baseline: 1.1165x; 1.0272x over previous
#include <cuda_runtime.h>
#include <cuda_fp16.h>
#include <cstdint>
#include <stdint.h>
#include <math.h>

#define Dm 1024
#define Fm 4096
#define Em 8
#define Tm 4096

#define BM 128
#define BN 128
#define BK 32
#define AST (BK + 8)   // 40 halfs = 80B rows -> conflict-free ldmatrix, 16B-aligned
#define BST (BK + 8)

// ---- scratch (device globals; allocation is forbidden) ----
// fixed per-expert regions: expert e owns rows [e*Tm, e*Tm + g_cnt[e])
__device__ __half g_W1h[(size_t)Em * Fm * Dm];      // W1 transposed fp16: [e][f][d]
__device__ __half g_W2h[(size_t)Em * Dm * Fm];      // W2 transposed fp16: [e][d][f]
__device__ __half g_Xg[(size_t)Em * Tm * Dm];       // gathered tokens fp16 (per-expert regions)
__device__ __half g_H [(size_t)Em * Tm * Fm];       // GELU activations fp16
__device__ float  g_Y [(size_t)Em * Tm * Dm];       // expert outputs fp32
__device__ int   g_cnt[Em];
__device__ int   g_te[Tm];            // e0 | e1<<8
__device__ int   g_tslot[2 * Tm];     // absolute slot of (token, k)
__device__ float g_tw[2 * Tm];        // routing weights

// ---------------- init counters ----------------
__global__ void init_kernel() {
    if (threadIdx.x < Em) g_cnt[threadIdx.x] = 0;
}

// ---- fused router: coalesced Wr loads -> top2 -> softmax -> gather ----
__global__ __launch_bounds__(256) void route_gather_kernel(const float* __restrict__ x,
                                                           const float* __restrict__ Wr,
                                                           const float* __restrict__ br) {
    int t = blockIdx.x;
    int tid = threadIdx.x;
    __shared__ __align__(16) float xrow[Dm];
    __shared__ float red[8][2][4];             // [warp][parity][expert-in-group]
    __shared__ float logits[Em];
    __shared__ int   sslot[2];

    // coalesced float4 load of x row
    float4 xv = ((const float4*)(x + (size_t)t * Dm))[tid];
    ((float4*)xrow)[tid] = xv;
    __syncthreads();

    // coalesced Wr accumulate: 8 float4 loads per thread
    float acc[4] = {0.f, 0.f, 0.f, 0.f};
    const float4* Wr4 = (const float4*)Wr;
    #pragma unroll
    for (int i = 0; i < 8; i++) {
        int idx = tid + i * 256;               // 0..2047
        float4 w = Wr4[idx];
        float xd = xrow[idx >> 1];
        acc[0] += xd * w.x; acc[1] += xd * w.y;
        acc[2] += xd * w.z; acc[3] += xd * w.w;
    }
    // butterfly over bits 1..4: lane 0 holds parity-0 sums, lane 1 parity-1
    #pragma unroll
    for (int o = 2; o <= 16; o <<= 1) {
        #pragma unroll
        for (int k = 0; k < 4; k++) acc[k] += __shfl_xor_sync(0xffffffffu, acc[k], o);
    }
    int warp = tid >> 5, lane = tid & 31;
    if (lane < 2) {
        #pragma unroll
        for (int k = 0; k < 4; k++) red[warp][lane][k] = acc[k];
    }
    __syncthreads();
    if (tid < Em) {
        int g = tid >> 2, k = tid & 3;
        float s = br[tid];
        #pragma unroll
        for (int w = 0; w < 8; w++) s += red[w][g][k];
        logits[tid] = s;
    }
    __syncthreads();

    if (tid == 0) {
        int i0 = 0; float v0 = logits[0];
        #pragma unroll
        for (int e = 1; e < Em; e++) if (logits[e] > v0) { v0 = logits[e]; i0 = e; }
        int i1 = -1; float v1 = -1e30f;
        #pragma unroll
        for (int e = 0; e < Em; e++) if (e != i0 && logits[e] > v1) { v1 = logits[e]; i1 = e; }
        float e1 = expf(v1 - v0);
        float inv = 1.0f / (1.0f + e1);
        int s0 = atomicAdd(&g_cnt[i0], 1);
        int s1 = atomicAdd(&g_cnt[i1], 1);
        int a0 = i0 * Tm + s0, a1 = i1 * Tm + s1;
        sslot[0] = a0; sslot[1] = a1;
        g_te[t] = i0 | (i1 << 8);
        g_tslot[2 * t] = a0; g_tslot[2 * t + 1] = a1;
        g_tw[2 * t] = inv;   g_tw[2 * t + 1] = e1 * inv;
    }
    __syncthreads();

    // write fp16 row into both expert slots: one 8B store per slot per thread
    int a0 = sslot[0], a1 = sslot[1];
    float4 v = ((const float4*)xrow)[tid];
    __half2 h0 = __floats2half2_rn(v.x, v.y);
    __half2 h1 = __floats2half2_rn(v.z, v.w);
    uint2 u;
    u.x = *(unsigned*)&h0;
    u.y = *(unsigned*)&h1;
    *(uint2*)(g_Xg + (size_t)a0 * Dm + tid * 4) = u;
    *(uint2*)(g_Xg + (size_t)a1 * Dm + tid * 4) = u;
}

// ---------------- weight convert + transpose: [e][K][N] f32 -> [e][N][K] f16 ----------------
// Tile 32(k) x 64(n). float4 reads, smem transpose, float4 (8-half) writes.
template <int K, int N, bool IS_W1>
__global__ __launch_bounds__(256) void convert_w_kernel(const float* __restrict__ W) {
    __shared__ float tile[32][65];
    int e = blockIdx.z;
    int n0 = blockIdx.x * 64, k0 = blockIdx.y * 32;
    const float* src = W + (size_t)e * K * N;                   // [K][N]
    __half* dst = (IS_W1 ? g_W1h : g_W2h) + (size_t)e * K * N;  // [N][K]
    int tid = threadIdx.x;

    // read 32x64 floats = 512 float4, 2 per thread (coalesced)
    #pragma unroll
    for (int it = 0; it < 2; it++) {
        int idx = it * 256 + tid;
        int kl = idx >> 4, n4 = idx & 15;
        float4 v = *(const float4*)(src + (size_t)(k0 + kl) * N + n0 + n4 * 4);
        tile[kl][n4 * 4 + 0] = v.x;
        tile[kl][n4 * 4 + 1] = v.y;
        tile[kl][n4 * 4 + 2] = v.z;
        tile[kl][n4 * 4 + 3] = v.w;
    }
    __syncthreads();

    // write: thread -> 8 consecutive k's of one dst row (16B store)
    // smem banks: addr=(8p+i)*65+nl -> (8p+i+nl) mod 32, distinct per i. conflict-free.
    {
        int nl = tid >> 2, p = tid & 3;     // 64 rows x 4 chunks
        __half h[8];
        #pragma unroll
        for (int i = 0; i < 8; i++) h[i] = __float2half_rn(tile[p * 8 + i][nl]);
        *(float4*)(dst + (size_t)(n0 + nl) * K + k0 + p * 8) = *(float4*)h;
    }
}

// ---------------- fp16 mma.sync grouped GEMM (ldmatrix frag loads) ----------------
#define MMA_F16(d, a, b)                                                      \
    asm volatile(                                                             \
        "mma.sync.aligned.m16n8k16.row.col.f32.f16.f16.f32 "                  \
        "{%0,%1,%2,%3}, {%4,%5,%6,%7}, {%8,%9}, {%0,%1,%2,%3};"               \
        : "+f"(d[0]), "+f"(d[1]), "+f"(d[2]), "+f"(d[3])                      \
        : "r"(a[0]), "r"(a[1]), "r"(a[2]), "r"(a[3]), "r"(b[0]), "r"(b[1]))

#define LDSM4(r0, r1, r2, r3, addr)                                           \
    asm volatile("ldmatrix.sync.aligned.m8n8.x4.shared.b16 {%0,%1,%2,%3}, [%4];" \
                 : "=r"(r0), "=r"(r1), "=r"(r2), "=r"(r3) : "r"(addr))

// PHASE1: A=g_Xg (K=Dm), B=g_W1h [e][F][D], O=g_H (bias+GELU, fp16)
// PHASE2: A=g_H  (K=Fm), B=g_W2h [e][D][F], O=g_Y (raw fp32)
template <bool PHASE1>
__global__ __launch_bounds__(256, 2) void gemm_kernel(const float* __restrict__ bias) {
    const int K   = PHASE1 ? Dm : Fm;
    const int Nt  = PHASE1 ? Fm : Dm;
    const int KT  = K / BK;

    int e = blockIdx.z;
    int cnt = g_cnt[e];
    int mBase = blockIdx.y * BM;
    if (mBase >= cnt) return;
    int off = e * Tm;
    int nBase = blockIdx.x * BN;

    const __half* A  = (PHASE1 ? g_Xg : g_H) + (size_t)(off + mBase) * K;
    const __half* Bp = (PHASE1 ? g_W1h : g_W2h) + (size_t)e * (size_t)K * (size_t)Nt
                       + (size_t)nBase * K;   // rows = n, cols = k

    __shared__ __half As[2][BM][AST];
    __shared__ __half Bs[2][BN][BST];

    int tid = threadIdx.x;
    int wid = tid >> 5, lane = tid & 31;
    int wm = wid & 3, wn = wid >> 2;      // 4 x 2 warp grid, 32(M) x 64(N) per warp
    int r = lane >> 2, c = lane & 3;

    float acc[2][8][4];
    #pragma unroll
    for (int mi = 0; mi < 2; mi++)
        #pragma unroll
        for (int ni = 0; ni < 8; ni++)
            #pragma unroll
            for (int q = 0; q < 4; q++) acc[mi][ni][q] = 0.f;

    unsigned asb = (unsigned)__cvta_generic_to_shared(&As[0][0][0]);
    unsigned bsb = (unsigned)__cvta_generic_to_shared(&Bs[0][0][0]);

    int q8 = lane >> 3, rr = lane & 7;
    unsigned offA = (unsigned)(((wm * 32 + (q8 & 1) * 8 + rr) * AST + (q8 >> 1) * 8) * 2);
    unsigned offB = (unsigned)(((wn * 64 + (q8 >> 1) * 8 + rr) * BST + (q8 & 1) * 8) * 2);

    auto load_stage = [&](int ktIdx, int buf) {
        int k0 = ktIdx * BK;
        unsigned asx = asb + (unsigned)buf * (BM * AST * 2);
        unsigned bsx = bsb + (unsigned)buf * (BN * BST * 2);
        #pragma unroll
        for (int i = 0; i < 2; i++) {
            int ch = tid + i * 256;
            int row = ch >> 2, kc = (ch & 3) * 8;
            const __half* src = A + (size_t)row * K + k0 + kc;
            unsigned dst = asx + (unsigned)(row * AST + kc) * 2u;
            asm volatile("cp.async.cg.shared.global [%0], [%1], 16;" :: "r"(dst), "l"(src));
        }
        #pragma unroll
        for (int i = 0; i < 2; i++) {
            int ch = tid + i * 256;
            int row = ch >> 2, kc = (ch & 3) * 8;
            const __half* src = Bp + (size_t)row * K + k0 + kc;
            unsigned dst = bsx + (unsigned)(row * BST + kc) * 2u;
            asm volatile("cp.async.cg.shared.global [%0], [%1], 16;" :: "r"(dst), "l"(src));
        }
        asm volatile("cp.async.commit_group;");
    };

    load_stage(0, 0);

    for (int kt = 0; kt < KT; ++kt) {
        int cur = kt & 1;
        asm volatile("cp.async.wait_group 0;");
        __syncthreads();
        if (kt + 1 < KT) load_stage(kt + 1, cur ^ 1);

        unsigned aS = asb + (unsigned)cur * (BM * AST * 2) + offA;
        unsigned bS = bsb + (unsigned)cur * (BN * BST * 2) + offB;

        #pragma unroll
        for (int ks = 0; ks < 2; ++ks) {
            unsigned kkb = (unsigned)(ks * 16 * 2);
            unsigned a[2][4];
            LDSM4(a[0][0], a[0][1], a[0][2], a[0][3], aS + kkb);
            LDSM4(a[1][0], a[1][1], a[1][2], a[1][3], aS + kkb + 16u * AST * 2u);
            unsigned b[8][2];
            #pragma unroll
            for (int g = 0; g < 4; ++g) {
                LDSM4(b[2 * g][0], b[2 * g][1], b[2 * g + 1][0], b[2 * g + 1][1],
                      bS + kkb + (unsigned)g * 16u * BST * 2u);
            }
            #pragma unroll
            for (int mi = 0; mi < 2; ++mi)
                #pragma unroll
                for (int ni = 0; ni < 8; ++ni)
                    MMA_F16(acc[mi][ni], a[mi], b[ni]);
        }
    }

    // ---- epilogue ----
    #pragma unroll
    for (int mi = 0; mi < 2; ++mi) {
        #pragma unroll
        for (int hh = 0; hh < 2; ++hh) {
            int m = wm * 32 + mi * 16 + r + hh * 8;
            if (mBase + m < cnt) {
                size_t slot = (size_t)(off + mBase + m);
                #pragma unroll
                for (int ni = 0; ni < 8; ++ni) {
                    int col = wn * 64 + ni * 8 + 2 * c;
                    float v0 = acc[mi][ni][hh * 2 + 0];
                    float v1 = acc[mi][ni][hh * 2 + 1];
                    if (PHASE1) {
                        v0 += bias[(size_t)e * Fm + nBase + col];
                        v1 += bias[(size_t)e * Fm + nBase + col + 1];
                        v0 = 0.5f * v0 * (1.0f + erff(v0 * 0.70710678118654752440f));
                        v1 = 0.5f * v1 * (1.0f + erff(v1 * 0.70710678118654752440f));
                        *(__half2*)(g_H + slot * Fm + nBase + col) = __floats2half2_rn(v0, v1);
                    } else {
                        *(float2*)(g_Y + slot * Dm + nBase + col) = make_float2(v0, v1);
                    }
                }
            }
        }
    }
}

// ---------------- combine: out[t] = sum_k w_k * (Y[slot_k] + b2[e_k]) ----------------
__global__ void combine_kernel(float* __restrict__ out,
                               const float* __restrict__ b2) {
    int t = blockIdx.x;
    int p = g_te[t];
    int e0 = p & 255, e1 = p >> 8;
    float w0 = g_tw[2 * t], w1 = g_tw[2 * t + 1];
    int s0 = g_tslot[2 * t], s1 = g_tslot[2 * t + 1];
    int d = threadIdx.x;
    float4 y0 = ((const float4*)(g_Y + (size_t)s0 * Dm))[d];
    float4 y1 = ((const float4*)(g_Y + (size_t)s1 * Dm))[d];
    float4 c0 = ((const float4*)(b2 + (size_t)e0 * Dm))[d];
    float4 c1 = ((const float4*)(b2 + (size_t)e1 * Dm))[d];
    float4 o;
    o.x = w0 * (y0.x + c0.x) + w1 * (y1.x + c1.x);
    o.y = w0 * (y0.y + c0.y) + w1 * (y1.y + c1.y);
    o.z = w0 * (y0.z + c0.z) + w1 * (y1.z + c1.z);
    o.w = w0 * (y0.w + c0.w) + w1 * (y1.w + c1.w);
    ((float4*)(out + (size_t)t * Dm))[d] = o;
}

extern "C" void kernel_launch(void* const* d_in, const int* in_sizes, int n_in,
                              void* d_out, int out_size) {
    const float* x  = (const float*)d_in[0];
    const float* Wr = (const float*)d_in[1];
    const float* br = (const float*)d_in[2];
    const float* W1 = (const float*)d_in[3];
    const float* b1 = (const float*)d_in[4];
    const float* W2 = (const float*)d_in[5];
    const float* b2 = (const float*)d_in[6];
    float* out = (float*)d_out;

    // Side stream + events (created once on first, uncaptured, call).
    static cudaStream_t sW = nullptr;
    static cudaEvent_t evFork = nullptr, evW1 = nullptr, evW2 = nullptr;
    static bool streamOk = false;
    if (!sW) {
        streamOk =
            cudaStreamCreateWithFlags(&sW, cudaStreamNonBlocking) == cudaSuccess &&
            cudaEventCreateWithFlags(&evFork, cudaEventDisableTiming) == cudaSuccess &&
            cudaEventCreateWithFlags(&evW1,   cudaEventDisableTiming) == cudaSuccess &&
            cudaEventCreateWithFlags(&evW2,   cudaEventDisableTiming) == cudaSuccess;
    }

    dim3 gW1(Fm / 64, Dm / 32, Em);
    dim3 gW2(Dm / 64, Fm / 32, Em);

    if (streamOk) {
        cudaEventRecord(evFork, 0);
        cudaStreamWaitEvent(sW, evFork, 0);
        convert_w_kernel<Dm, Fm, true ><<<gW1, 256, 0, sW>>>(W1);
        cudaEventRecord(evW1, sW);
        convert_w_kernel<Fm, Dm, false><<<gW2, 256, 0, sW>>>(W2);
        cudaEventRecord(evW2, sW);
    } else {
        convert_w_kernel<Dm, Fm, true ><<<gW1, 256>>>(W1);
        convert_w_kernel<Fm, Dm, false><<<gW2, 256>>>(W2);
    }

    init_kernel<<<1, 32>>>();
    route_gather_kernel<<<Tm, 256>>>(x, Wr, br);

    if (streamOk) cudaStreamWaitEvent(0, evW1, 0);    // W1h ready
    dim3 g1(Fm / BN, Tm / BM, Em);
    gemm_kernel<true><<<g1, 256>>>(b1);

    if (streamOk) cudaStreamWaitEvent(0, evW2, 0);    // W2h ready
    dim3 g2(Dm / BN, Tm / BM, Em);
    gemm_kernel<false><<<g2, 256>>>(b2);

    combine_kernel<<<Tm, 256>>>(out, b2);
}

// round 16
// speedup vs baseline: 1.1377x; 1.0190x over previous
#include <cuda_runtime.h>
#include <cuda_fp16.h>
#include <cstdint>
#include <stdint.h>
#include <math.h>

#define Dm 1024
#define Fm 4096
#define Em 8
#define Tm 4096

#define BM 128
#define BN 128
#define BK 32
#define AST (BK + 8)   // 40 halfs = 80B rows -> conflict-free ldmatrix, 16B-aligned
#define BST (BK + 8)

// ---- scratch (device globals; allocation is forbidden) ----
// fixed per-expert regions: expert e owns rows [e*Tm, e*Tm + g_cnt[e])
__device__ __half g_W1h[(size_t)Em * Fm * Dm];      // W1 transposed fp16: [e][f][d]
__device__ __half g_W2h[(size_t)Em * Dm * Fm];      // W2 transposed fp16: [e][d][f]
__device__ __half g_Xg[(size_t)Em * Tm * Dm];       // gathered tokens fp16 (per-expert regions)
__device__ __half g_H [(size_t)Em * Tm * Fm];       // GELU activations fp16
__device__ float  g_Y [(size_t)Em * Tm * Dm];       // expert outputs fp32
__device__ int   g_cnt[Em];                         // zero-init; re-armed by combine tail
__device__ int   g_te[Tm];            // e0 | e1<<8
__device__ int   g_tslot[2 * Tm];     // absolute slot of (token, k)
__device__ float g_tw[2 * Tm];        // routing weights

// ---- fused router: coalesced Wr loads -> top2 -> softmax -> gather ----
__global__ __launch_bounds__(256) void route_gather_kernel(const float* __restrict__ x,
                                                           const float* __restrict__ Wr,
                                                           const float* __restrict__ br) {
    int t = blockIdx.x;
    int tid = threadIdx.x;
    __shared__ __align__(16) float xrow[Dm];
    __shared__ float red[8][2][4];             // [warp][parity][expert-in-group]
    __shared__ float logits[Em];
    __shared__ int   sslot[2];

    // coalesced float4 load of x row
    float4 xv = ((const float4*)(x + (size_t)t * Dm))[tid];
    ((float4*)xrow)[tid] = xv;
    __syncthreads();

    // coalesced Wr accumulate: 8 float4 loads per thread
    float acc[4] = {0.f, 0.f, 0.f, 0.f};
    const float4* Wr4 = (const float4*)Wr;
    #pragma unroll
    for (int i = 0; i < 8; i++) {
        int idx = tid + i * 256;               // 0..2047
        float4 w = Wr4[idx];
        float xd = xrow[idx >> 1];
        acc[0] += xd * w.x; acc[1] += xd * w.y;
        acc[2] += xd * w.z; acc[3] += xd * w.w;
    }
    // butterfly over bits 1..4: lane 0 holds parity-0 sums, lane 1 parity-1
    #pragma unroll
    for (int o = 2; o <= 16; o <<= 1) {
        #pragma unroll
        for (int k = 0; k < 4; k++) acc[k] += __shfl_xor_sync(0xffffffffu, acc[k], o);
    }
    int warp = tid >> 5, lane = tid & 31;
    if (lane < 2) {
        #pragma unroll
        for (int k = 0; k < 4; k++) red[warp][lane][k] = acc[k];
    }
    __syncthreads();
    if (tid < Em) {
        int g = tid >> 2, k = tid & 3;
        float s = br[tid];
        #pragma unroll
        for (int w = 0; w < 8; w++) s += red[w][g][k];
        logits[tid] = s;
    }
    __syncthreads();

    if (tid == 0) {
        int i0 = 0; float v0 = logits[0];
        #pragma unroll
        for (int e = 1; e < Em; e++) if (logits[e] > v0) { v0 = logits[e]; i0 = e; }
        int i1 = -1; float v1 = -1e30f;
        #pragma unroll
        for (int e = 0; e < Em; e++) if (e != i0 && logits[e] > v1) { v1 = logits[e]; i1 = e; }
        float e1 = expf(v1 - v0);
        float inv = 1.0f / (1.0f + e1);
        int s0 = atomicAdd(&g_cnt[i0], 1);
        int s1 = atomicAdd(&g_cnt[i1], 1);
        int a0 = i0 * Tm + s0, a1 = i1 * Tm + s1;
        sslot[0] = a0; sslot[1] = a1;
        g_te[t] = i0 | (i1 << 8);
        g_tslot[2 * t] = a0; g_tslot[2 * t + 1] = a1;
        g_tw[2 * t] = inv;   g_tw[2 * t + 1] = e1 * inv;
    }
    __syncthreads();

    // write fp16 row into both expert slots: one 8B store per slot per thread
    int a0 = sslot[0], a1 = sslot[1];
    float4 v = ((const float4*)xrow)[tid];
    __half2 h0 = __floats2half2_rn(v.x, v.y);
    __half2 h1 = __floats2half2_rn(v.z, v.w);
    uint2 u;
    u.x = *(unsigned*)&h0;
    u.y = *(unsigned*)&h1;
    *(uint2*)(g_Xg + (size_t)a0 * Dm + tid * 4) = u;
    *(uint2*)(g_Xg + (size_t)a1 * Dm + tid * 4) = u;
}

// ---------------- weight convert + transpose: [e][K][N] f32 -> [e][N][K] f16 ----------------
// Tile 32(k) x 64(n). float4 reads, smem transpose, float4 (8-half) writes.
template <int K, int N, bool IS_W1>
__global__ __launch_bounds__(256) void convert_w_kernel(const float* __restrict__ W) {
    __shared__ float tile[32][65];
    int e = blockIdx.z;
    int n0 = blockIdx.x * 64, k0 = blockIdx.y * 32;
    const float* src = W + (size_t)e * K * N;                   // [K][N]
    __half* dst = (IS_W1 ? g_W1h : g_W2h) + (size_t)e * K * N;  // [N][K]
    int tid = threadIdx.x;

    #pragma unroll
    for (int it = 0; it < 2; it++) {
        int idx = it * 256 + tid;
        int kl = idx >> 4, n4 = idx & 15;
        float4 v = *(const float4*)(src + (size_t)(k0 + kl) * N + n0 + n4 * 4);
        tile[kl][n4 * 4 + 0] = v.x;
        tile[kl][n4 * 4 + 1] = v.y;
        tile[kl][n4 * 4 + 2] = v.z;
        tile[kl][n4 * 4 + 3] = v.w;
    }
    __syncthreads();

    {
        int nl = tid >> 2, p = tid & 3;     // 64 rows x 4 chunks
        __half h[8];
        #pragma unroll
        for (int i = 0; i < 8; i++) h[i] = __float2half_rn(tile[p * 8 + i][nl]);
        *(float4*)(dst + (size_t)(n0 + nl) * K + k0 + p * 8) = *(float4*)h;
    }
}

// ---------------- fp16 mma.sync grouped GEMM (ldmatrix frag loads) ----------------
#define MMA_F16(d, a, b)                                                      \
    asm volatile(                                                             \
        "mma.sync.aligned.m16n8k16.row.col.f32.f16.f16.f32 "                  \
        "{%0,%1,%2,%3}, {%4,%5,%6,%7}, {%8,%9}, {%0,%1,%2,%3};"               \
        : "+f"(d[0]), "+f"(d[1]), "+f"(d[2]), "+f"(d[3])                      \
        : "r"(a[0]), "r"(a[1]), "r"(a[2]), "r"(a[3]), "r"(b[0]), "r"(b[1]))

#define LDSM4(r0, r1, r2, r3, addr)                                           \
    asm volatile("ldmatrix.sync.aligned.m8n8.x4.shared.b16 {%0,%1,%2,%3}, [%4];" \
                 : "=r"(r0), "=r"(r1), "=r"(r2), "=r"(r3) : "r"(addr))

// PHASE1: A=g_Xg (K=Dm), B=g_W1h [e][F][D], O=g_H (bias+GELU, fp16)
// PHASE2: A=g_H  (K=Fm), B=g_W2h [e][D][F], O=g_Y (raw fp32)
// eBase: first expert of this launch (grid.z covers 4 experts -> 2-stream packing)
template <bool PHASE1>
__global__ __launch_bounds__(256, 2) void gemm_kernel(const float* __restrict__ bias,
                                                      int eBase) {
    const int K   = PHASE1 ? Dm : Fm;
    const int Nt  = PHASE1 ? Fm : Dm;
    const int KT  = K / BK;

    int e = eBase + blockIdx.z;
    int cnt = g_cnt[e];
    int mBase = blockIdx.y * BM;
    if (mBase >= cnt) return;
    int off = e * Tm;
    int nBase = blockIdx.x * BN;

    const __half* A  = (PHASE1 ? g_Xg : g_H) + (size_t)(off + mBase) * K;
    const __half* Bp = (PHASE1 ? g_W1h : g_W2h) + (size_t)e * (size_t)K * (size_t)Nt
                       + (size_t)nBase * K;   // rows = n, cols = k

    __shared__ __half As[2][BM][AST];
    __shared__ __half Bs[2][BN][BST];

    int tid = threadIdx.x;
    int wid = tid >> 5, lane = tid & 31;
    int wm = wid & 3, wn = wid >> 2;      // 4 x 2 warp grid, 32(M) x 64(N) per warp
    int r = lane >> 2, c = lane & 3;

    float acc[2][8][4];
    #pragma unroll
    for (int mi = 0; mi < 2; mi++)
        #pragma unroll
        for (int ni = 0; ni < 8; ni++)
            #pragma unroll
            for (int q = 0; q < 4; q++) acc[mi][ni][q] = 0.f;

    unsigned asb = (unsigned)__cvta_generic_to_shared(&As[0][0][0]);
    unsigned bsb = (unsigned)__cvta_generic_to_shared(&Bs[0][0][0]);

    int q8 = lane >> 3, rr = lane & 7;
    unsigned offA = (unsigned)(((wm * 32 + (q8 & 1) * 8 + rr) * AST + (q8 >> 1) * 8) * 2);
    unsigned offB = (unsigned)(((wn * 64 + (q8 >> 1) * 8 + rr) * BST + (q8 & 1) * 8) * 2);

    auto load_stage = [&](int ktIdx, int buf) {
        int k0 = ktIdx * BK;
        unsigned asx = asb + (unsigned)buf * (BM * AST * 2);
        unsigned bsx = bsb + (unsigned)buf * (BN * BST * 2);
        #pragma unroll
        for (int i = 0; i < 2; i++) {
            int ch = tid + i * 256;
            int row = ch >> 2, kc = (ch & 3) * 8;
            const __half* src = A + (size_t)row * K + k0 + kc;
            unsigned dst = asx + (unsigned)(row * AST + kc) * 2u;
            asm volatile("cp.async.cg.shared.global [%0], [%1], 16;" :: "r"(dst), "l"(src));
        }
        #pragma unroll
        for (int i = 0; i < 2; i++) {
            int ch = tid + i * 256;
            int row = ch >> 2, kc = (ch & 3) * 8;
            const __half* src = Bp + (size_t)row * K + k0 + kc;
            unsigned dst = bsx + (unsigned)(row * BST + kc) * 2u;
            asm volatile("cp.async.cg.shared.global [%0], [%1], 16;" :: "r"(dst), "l"(src));
        }
        asm volatile("cp.async.commit_group;");
    };

    load_stage(0, 0);

    for (int kt = 0; kt < KT; ++kt) {
        int cur = kt & 1;
        asm volatile("cp.async.wait_group 0;");
        __syncthreads();
        if (kt + 1 < KT) load_stage(kt + 1, cur ^ 1);

        unsigned aS = asb + (unsigned)cur * (BM * AST * 2) + offA;
        unsigned bS = bsb + (unsigned)cur * (BN * BST * 2) + offB;

        #pragma unroll
        for (int ks = 0; ks < 2; ++ks) {
            unsigned kkb = (unsigned)(ks * 16 * 2);
            unsigned a[2][4];
            LDSM4(a[0][0], a[0][1], a[0][2], a[0][3], aS + kkb);
            LDSM4(a[1][0], a[1][1], a[1][2], a[1][3], aS + kkb + 16u * AST * 2u);
            unsigned b[8][2];
            #pragma unroll
            for (int g = 0; g < 4; ++g) {
                LDSM4(b[2 * g][0], b[2 * g][1], b[2 * g + 1][0], b[2 * g + 1][1],
                      bS + kkb + (unsigned)g * 16u * BST * 2u);
            }
            #pragma unroll
            for (int mi = 0; mi < 2; ++mi)
                #pragma unroll
                for (int ni = 0; ni < 8; ++ni)
                    MMA_F16(acc[mi][ni], a[mi], b[ni]);
        }
    }

    // ---- epilogue ----
    #pragma unroll
    for (int mi = 0; mi < 2; ++mi) {
        #pragma unroll
        for (int hh = 0; hh < 2; ++hh) {
            int m = wm * 32 + mi * 16 + r + hh * 8;
            if (mBase + m < cnt) {
                size_t slot = (size_t)(off + mBase + m);
                #pragma unroll
                for (int ni = 0; ni < 8; ++ni) {
                    int col = wn * 64 + ni * 8 + 2 * c;
                    float v0 = acc[mi][ni][hh * 2 + 0];
                    float v1 = acc[mi][ni][hh * 2 + 1];
                    if (PHASE1) {
                        v0 += bias[(size_t)e * Fm + nBase + col];
                        v1 += bias[(size_t)e * Fm + nBase + col + 1];
                        v0 = 0.5f * v0 * (1.0f + erff(v0 * 0.70710678118654752440f));
                        v1 = 0.5f * v1 * (1.0f + erff(v1 * 0.70710678118654752440f));
                        *(__half2*)(g_H + slot * Fm + nBase + col) = __floats2half2_rn(v0, v1);
                    } else {
                        *(float2*)(g_Y + slot * Dm + nBase + col) = make_float2(v0, v1);
                    }
                }
            }
        }
    }
}

// ---------------- combine: out[t] = sum_k w_k * (Y[slot_k] + b2[e_k]) ----------------
// Tail: block 0 re-arms g_cnt for the next launch (nothing later reads it).
__global__ void combine_kernel(float* __restrict__ out,
                               const float* __restrict__ b2) {
    int t = blockIdx.x;
    int p = g_te[t];
    int e0 = p & 255, e1 = p >> 8;
    float w0 = g_tw[2 * t], w1 = g_tw[2 * t + 1];
    int s0 = g_tslot[2 * t], s1 = g_tslot[2 * t + 1];
    int d = threadIdx.x;
    float4 y0 = ((const float4*)(g_Y + (size_t)s0 * Dm))[d];
    float4 y1 = ((const float4*)(g_Y + (size_t)s1 * Dm))[d];
    float4 c0 = ((const float4*)(b2 + (size_t)e0 * Dm))[d];
    float4 c1 = ((const float4*)(b2 + (size_t)e1 * Dm))[d];
    float4 o;
    o.x = w0 * (y0.x + c0.x) + w1 * (y1.x + c1.x);
    o.y = w0 * (y0.y + c0.y) + w1 * (y1.y + c1.y);
    o.z = w0 * (y0.z + c0.z) + w1 * (y1.z + c1.z);
    o.w = w0 * (y0.w + c0.w) + w1 * (y1.w + c1.w);
    ((float4*)(out + (size_t)t * Dm))[d] = o;

    if (blockIdx.x == 0 && threadIdx.x < Em) g_cnt[threadIdx.x] = 0;
}

extern "C" void kernel_launch(void* const* d_in, const int* in_sizes, int n_in,
                              void* d_out, int out_size) {
    const float* x  = (const float*)d_in[0];
    const float* Wr = (const float*)d_in[1];
    const float* br = (const float*)d_in[2];
    const float* W1 = (const float*)d_in[3];
    const float* b1 = (const float*)d_in[4];
    const float* W2 = (const float*)d_in[5];
    const float* b2 = (const float*)d_in[6];
    float* out = (float*)d_out;

    // Streams + events (created once on first, uncaptured, call).
    static cudaStream_t sW = nullptr, sC = nullptr;
    static cudaEvent_t evFork = nullptr, evW1 = nullptr, evW2 = nullptr;
    static cudaEvent_t evRoute = nullptr, evB = nullptr;
    static bool streamOk = false;
    if (!sW) {
        streamOk =
            cudaStreamCreateWithFlags(&sW, cudaStreamNonBlocking) == cudaSuccess &&
            cudaStreamCreateWithFlags(&sC, cudaStreamNonBlocking) == cudaSuccess &&
            cudaEventCreateWithFlags(&evFork,  cudaEventDisableTiming) == cudaSuccess &&
            cudaEventCreateWithFlags(&evW1,    cudaEventDisableTiming) == cudaSuccess &&
            cudaEventCreateWithFlags(&evW2,    cudaEventDisableTiming) == cudaSuccess &&
            cudaEventCreateWithFlags(&evRoute, cudaEventDisableTiming) == cudaSuccess &&
            cudaEventCreateWithFlags(&evB,     cudaEventDisableTiming) == cudaSuccess;
    }

    dim3 gW1(Fm / 64, Dm / 32, Em);
    dim3 gW2(Dm / 64, Fm / 32, Em);
    dim3 g1h(Fm / BN, Tm / BM, 4);   // GEMM1, 4 experts per launch
    dim3 g2h(Dm / BN, Tm / BM, 4);   // GEMM2, 4 experts per launch

    if (streamOk) {
        // converts on sW, concurrent with routing
        cudaEventRecord(evFork, 0);
        cudaStreamWaitEvent(sW, evFork, 0);
        convert_w_kernel<Dm, Fm, true ><<<gW1, 256, 0, sW>>>(W1);
        cudaEventRecord(evW1, sW);
        convert_w_kernel<Fm, Dm, false><<<gW2, 256, 0, sW>>>(W2);
        cudaEventRecord(evW2, sW);

        route_gather_kernel<<<Tm, 256>>>(x, Wr, br);
        cudaEventRecord(evRoute, 0);

        // half B chain on sC: G1(e4-7) -> G2(e4-7)
        cudaStreamWaitEvent(sC, evRoute, 0);
        cudaStreamWaitEvent(sC, evW1, 0);
        gemm_kernel<true><<<g1h, 256, 0, sC>>>(b1, 4);
        cudaStreamWaitEvent(sC, evW2, 0);
        gemm_kernel<false><<<g2h, 256, 0, sC>>>(b2, 4);
        cudaEventRecord(evB, sC);

        // half A chain on default: G1(e0-3) -> G2(e0-3)
        cudaStreamWaitEvent(0, evW1, 0);
        gemm_kernel<true><<<g1h, 256>>>(b1, 0);
        cudaStreamWaitEvent(0, evW2, 0);
        gemm_kernel<false><<<g2h, 256>>>(b2, 0);

        cudaStreamWaitEvent(0, evB, 0);
        combine_kernel<<<Tm, 256>>>(out, b2);
    } else {
        convert_w_kernel<Dm, Fm, true ><<<gW1, 256>>>(W1);
        convert_w_kernel<Fm, Dm, false><<<gW2, 256>>>(W2);
        route_gather_kernel<<<Tm, 256>>>(x, Wr, br);
        gemm_kernel<true><<<g1h, 256>>>(b1, 0);
        gemm_kernel<true><<<g1h, 256>>>(b1, 4);
        gemm_kernel<false><<<g2h, 256>>>(b2, 0);
        gemm_kernel<false><<<g2h, 256>>>(b2, 4);
        combine_kernel<<<Tm, 256>>>(out, b2);
    }
}